// round 13
// baseline (speedup 1.0000x reference)
#include <cuda_runtime.h>
#include <cuda_bf16.h>
#include <math.h>
#include <stdint.h>

#define NF    20000
#define NMB   5000
#define EFFN  100000
#define EFFP  100096           // EFFN padded to 128
#define EMFN  80000
#define DIMV  64
#define KWN   512
#define SLAB  500
#define NSLAB 40
#define W2N   32768            // KWN * DIMV

#define A_LD  24               // 16 k + 8 pad (ushort)
#define B_LD  136              // 128 n + 8 pad (ushort)

typedef unsigned long long u64t;

// ---------------- device scratch (__device__ globals; no allocations) ----------------
__device__ unsigned short g_h0_hi[(size_t)EFFP * KWN];  // 102.5 MB
__device__ unsigned short g_h0_lo[(size_t)EFFP * KWN];
__device__ float    g_h [(size_t)EFFN * KWN];           // 204.8 MB
__device__ float    g_M [(size_t)SLAB * W2N];           // 65.5 MB
__device__ unsigned short g_W2T_hi[(size_t)DIMV * W2N]; // 4 MB  [d][n=k*64+f]
__device__ unsigned short g_W2T_lo[(size_t)DIMV * W2N];
__device__ unsigned short g_Wk1_hi[KWN * KWN];          // 512 KB [k][n]
__device__ unsigned short g_Wk1_lo[KWN * KWN];
__device__ unsigned short g_x_hi[(NF + 512) * DIMV];    // 2.6 MB
__device__ unsigned short g_x_lo[(NF + 512) * DIMV];
__device__ float    g_q [NF * DIMV];
__device__ float    g_kk[NMB * DIMV];
__device__ float    g_v [NMB * DIMV];
__device__ float    g_c [NF * DIMV];
__device__ float    g_score[EMFN];
__device__ float    g_av[EMFN];
__device__ unsigned g_mkey[NF];
__device__ float    g_z[NF];
__device__ float    g_xc[NF * DIMV];
__device__ float    g_base[NF * DIMV];
__device__ float    g_aggr[NF * DIMV];
__device__ int      g_cnt[NF];
__device__ int      g_off[NF + 1];
__device__ int      g_pos[NF];
__device__ int      g_perm[EFFN];
__device__ float    g_ss[2 * DIMV];

// ---------------- helpers ----------------
__device__ __forceinline__ unsigned kenc(float f) {
    unsigned b = __float_as_uint(f);
    return (b & 0x80000000u) ? ~b : (b | 0x80000000u);
}
__device__ __forceinline__ float kdec(unsigned u) {
    return (u & 0x80000000u) ? __uint_as_float(u ^ 0x80000000u) : __uint_as_float(~u);
}
__device__ __forceinline__ float silu(float y) { return y / (1.f + expf(-y)); }

__device__ __forceinline__ u64t pack_dup(float x) {
    u64t r; asm("mov.b64 %0, {%1, %1};" : "=l"(r) : "r"(__float_as_uint(x))); return r;
}
__device__ __forceinline__ u64t pack2(float lo, float hi) {
    u64t r; asm("mov.b64 %0, {%1, %2};" : "=l"(r) : "r"(__float_as_uint(lo)), "r"(__float_as_uint(hi))); return r;
}
__device__ __forceinline__ void fma2(u64t& d, u64t a, u64t b) {
    asm("fma.rn.f32x2 %0, %1, %2, %0;" : "+l"(d) : "l"(a), "l"(b));
}

__device__ __forceinline__ uint32_t smem_u32(const void* p) {
    uint32_t a;
    asm("{ .reg .u64 t; cvta.to.shared.u64 t, %1; cvt.u32.u64 %0, t; }" : "=r"(a) : "l"(p));
    return a;
}
__device__ __forceinline__ void cpa16(void* dst_smem, const void* src) {
    asm volatile("cp.async.ca.shared.global [%0], [%1], 16;"
                 :: "r"(smem_u32(dst_smem)), "l"(src));
}
#define CPA_COMMIT() asm volatile("cp.async.commit_group;")
#define CPA_WAIT1()  asm volatile("cp.async.wait_group 1;")
#define CPA_WAIT0()  asm volatile("cp.async.wait_group 0;")

__device__ __forceinline__ void ldsm4(uint32_t& r0, uint32_t& r1, uint32_t& r2, uint32_t& r3, uint32_t a) {
    asm volatile("ldmatrix.sync.aligned.m8n8.x4.shared.b16 {%0,%1,%2,%3}, [%4];"
        : "=r"(r0), "=r"(r1), "=r"(r2), "=r"(r3) : "r"(a));
}
__device__ __forceinline__ void ldsm4t(uint32_t& r0, uint32_t& r1, uint32_t& r2, uint32_t& r3, uint32_t a) {
    asm volatile("ldmatrix.sync.aligned.m8n8.x4.trans.shared.b16 {%0,%1,%2,%3}, [%4];"
        : "=r"(r0), "=r"(r1), "=r"(r2), "=r"(r3) : "r"(a));
}
__device__ __forceinline__ void mma_bf16(float* c, const uint32_t* a, uint32_t b0, uint32_t b1) {
    asm volatile(
        "mma.sync.aligned.m16n8k16.row.col.f32.bf16.bf16.f32 "
        "{%0,%1,%2,%3}, {%4,%5,%6,%7}, {%8,%9}, {%0,%1,%2,%3};"
        : "+f"(c[0]), "+f"(c[1]), "+f"(c[2]), "+f"(c[3])
        : "r"(a[0]), "r"(a[1]), "r"(a[2]), "r"(a[3]), "r"(b0), "r"(b1));
}

// warp-tile kstep: c[2][8][4] += bf16x3( A[32x16] , B[16x64] )
__device__ __forceinline__ void warp_kstep(float c[2][8][4],
        const unsigned short* Ahi, const unsigned short* Alo,
        const unsigned short* Bhi, const unsigned short* Blo,
        int warp_m, int warp_n, int lane) {
    int arow = lane & 15;
    int acol = (lane >> 4) << 3;
    uint32_t ahi[2][4], alo[2][4];
#pragma unroll
    for (int mi = 0; mi < 2; mi++) {
        int r = warp_m * 32 + mi * 16 + arow;
        ldsm4(ahi[mi][0], ahi[mi][1], ahi[mi][2], ahi[mi][3], smem_u32(Ahi + r * A_LD + acol));
        ldsm4(alo[mi][0], alo[mi][1], alo[mi][2], alo[mi][3], smem_u32(Alo + r * A_LD + acol));
    }
#pragma unroll
    for (int nh = 0; nh < 2; nh++) {
        uint32_t bhi[2][4], blo[2][4];
#pragma unroll
        for (int ni = 0; ni < 2; ni++) {
            int ncol = warp_n * 64 + nh * 32 + ni * 16 + acol;
            ldsm4t(bhi[ni][0], bhi[ni][1], bhi[ni][2], bhi[ni][3], smem_u32(Bhi + arow * B_LD + ncol));
            ldsm4t(blo[ni][0], blo[ni][1], blo[ni][2], blo[ni][3], smem_u32(Blo + arow * B_LD + ncol));
        }
#pragma unroll
        for (int mi = 0; mi < 2; mi++)
#pragma unroll
            for (int ni = 0; ni < 2; ni++) {
                int n8 = nh * 4 + ni * 2;
                mma_bf16(c[mi][n8],     ahi[mi], bhi[ni][0], bhi[ni][1]);
                mma_bf16(c[mi][n8 + 1], ahi[mi], bhi[ni][2], bhi[ni][3]);
                mma_bf16(c[mi][n8],     ahi[mi], blo[ni][0], blo[ni][1]);
                mma_bf16(c[mi][n8 + 1], ahi[mi], blo[ni][2], blo[ni][3]);
                mma_bf16(c[mi][n8],     alo[mi], bhi[ni][0], bhi[ni][1]);
                mma_bf16(c[mi][n8 + 1], alo[mi], bhi[ni][2], bhi[ni][3]);
            }
    }
}

// ---------------- tiny utility kernels ----------------
__global__ void zero_u32(unsigned* p, int n) {
    for (int i = blockIdx.x * blockDim.x + threadIdx.x; i < n; i += gridDim.x * blockDim.x)
        p[i] = 0u;
}

__global__ void conv_wk1(const float* __restrict__ Wk1) {
    int idx = blockIdx.x * blockDim.x + threadIdx.x;
    if (idx >= KWN * KWN) return;
    float v = Wk1[idx];
    __nv_bfloat16 bh = __float2bfloat16_rn(v);
    __nv_bfloat16 bl = __float2bfloat16_rn(v - __bfloat162float(bh));
    g_Wk1_hi[idx] = __bfloat16_as_ushort(bh);
    g_Wk1_lo[idx] = __bfloat16_as_ushort(bl);
}

__global__ void conv_w2t(const float* __restrict__ Wk2) {
    int idx = blockIdx.x * blockDim.x + threadIdx.x;
    if (idx >= DIMV * W2N) return;
    int d = idx >> 15;
    int r = idx & 32767;
    int k = r >> 6;
    int f = r & 63;
    float v = Wk2[k * 4096 + d * 64 + f];
    __nv_bfloat16 bh = __float2bfloat16_rn(v);
    __nv_bfloat16 bl = __float2bfloat16_rn(v - __bfloat162float(bh));
    g_W2T_hi[idx] = __bfloat16_as_ushort(bh);
    g_W2T_lo[idx] = __bfloat16_as_ushort(bl);
}

__global__ void conv_x(const float* __restrict__ x_flow) {
    int idx = blockIdx.x * blockDim.x + threadIdx.x;
    if (idx >= NF * DIMV) return;
    float v = x_flow[idx];
    __nv_bfloat16 bh = __float2bfloat16_rn(v);
    __nv_bfloat16 bl = __float2bfloat16_rn(v - __bfloat162float(bh));
    g_x_hi[idx] = __bfloat16_as_ushort(bh);
    g_x_lo[idx] = __bfloat16_as_ushort(bl);
}

// h0 = relu(ea @ Wk0 + bk0), stored hi/lo bf16. 8 edges per block, 32 threads/edge.
__global__ void __launch_bounds__(256)
h0_split(const float* __restrict__ ea_ff, const float* __restrict__ Wk0,
         const float* __restrict__ bk0) {
    __shared__ float sW[6][KWN];
    __shared__ float sb[KWN];
    int tid = threadIdx.x;
    for (int i = tid; i < 6 * KWN; i += 256) sW[i / KWN][i % KWN] = Wk0[i];
    for (int i = tid; i < KWN; i += 256) sb[i] = bk0[i];
    __syncthreads();
    int e = blockIdx.x * 8 + (tid >> 5);
    int lane = tid & 31;
    int n0 = lane * 16;
    float a[6];
#pragma unroll
    for (int j = 0; j < 6; j++) a[j] = ea_ff[e * 6 + j];
    unsigned short h[16], l[16];
#pragma unroll
    for (int i = 0; i < 16; i++) {
        int n = n0 + i;
        float v = sb[n];
#pragma unroll
        for (int j = 0; j < 6; j++) v = fmaf(a[j], sW[j][n], v);
        v = fmaxf(v, 0.f);
        __nv_bfloat16 bh = __float2bfloat16_rn(v);
        __nv_bfloat16 bl = __float2bfloat16_rn(v - __bfloat162float(bh));
        h[i] = __bfloat16_as_ushort(bh);
        l[i] = __bfloat16_as_ushort(bl);
    }
    size_t dst = (size_t)e * KWN + n0;
    *(uint4*)&g_h0_hi[dst]     = *(uint4*)&h[0];
    *(uint4*)&g_h0_hi[dst + 8] = *(uint4*)&h[8];
    *(uint4*)&g_h0_lo[dst]     = *(uint4*)&l[0];
    *(uint4*)&g_h0_lo[dst + 8] = *(uint4*)&l[8];
}

// ---------------- HMMA GEMM 1 (pipelined): h = relu(h0 @ Wk1 + bk1) ----------------
__global__ void __launch_bounds__(256)
gemm_h_mma(const float* __restrict__ bk1) {
    __shared__ __align__(16) unsigned short Ahi[2][128 * A_LD], Alo[2][128 * A_LD];
    __shared__ __align__(16) unsigned short Bhi[2][16 * B_LD],  Blo[2][16 * B_LD];
    int tid = threadIdx.x, wid = tid >> 5, lane = tid & 31;
    int warp_m = wid & 3, warp_n = wid >> 2;
    int tm = blockIdx.y, tn = blockIdx.x;

    int ar = tid >> 1, ac = (tid & 1) * 8;
    int bk = tid >> 4, bc = (tid & 15) * 8;

    float c[2][8][4];
#pragma unroll
    for (int i = 0; i < 2; i++)
#pragma unroll
        for (int j = 0; j < 8; j++)
#pragma unroll
            for (int q = 0; q < 4; q++) c[i][j][q] = 0.f;

#define STAGE_H(s, kc) { \
    size_t asrc = (size_t)(tm * 128 + ar) * KWN + (kc) * 16 + ac; \
    cpa16(&Ahi[s][ar * A_LD + ac], g_h0_hi + asrc); \
    cpa16(&Alo[s][ar * A_LD + ac], g_h0_lo + asrc); \
    size_t bsrc = (size_t)((kc) * 16 + bk) * KWN + tn * 128 + bc; \
    cpa16(&Bhi[s][bk * B_LD + bc], g_Wk1_hi + bsrc); \
    cpa16(&Blo[s][bk * B_LD + bc], g_Wk1_lo + bsrc); \
    CPA_COMMIT(); }

    STAGE_H(0, 0);
    for (int kc = 0; kc < 32; kc++) {
        if (kc < 31) { STAGE_H((kc + 1) & 1, kc + 1); CPA_WAIT1(); }
        else         { CPA_WAIT0(); }
        __syncthreads();
        int b = kc & 1;
        warp_kstep(c, Ahi[b], Alo[b], Bhi[b], Blo[b], warp_m, warp_n, lane);
        __syncthreads();
    }
#undef STAGE_H

    int rbase = tm * 128 + warp_m * 32 + (lane >> 2);
    int cbase = tn * 128 + warp_n * 64 + (lane & 3) * 2;
#pragma unroll
    for (int mi = 0; mi < 2; mi++) {
#pragma unroll
        for (int n8 = 0; n8 < 8; n8++) {
            int col = cbase + n8 * 8;
            float b0 = bk1[col], b1 = bk1[col + 1];
            int r0 = rbase + mi * 16;
            if (r0 < EFFN) {
                float2 v = make_float2(fmaxf(c[mi][n8][0] + b0, 0.f), fmaxf(c[mi][n8][1] + b1, 0.f));
                *(float2*)&g_h[(size_t)r0 * KWN + col] = v;
            }
            int r1 = r0 + 8;
            if (r1 < EFFN) {
                float2 v = make_float2(fmaxf(c[mi][n8][2] + b0, 0.f), fmaxf(c[mi][n8][3] + b1, 0.f));
                *(float2*)&g_h[(size_t)r1 * KWN + col] = v;
            }
        }
    }
}

// ---------------- HMMA GEMM 2 (pipelined): M_slab = x_slab @ W2T, K=64 ----------------
__global__ void __launch_bounds__(256)
gemm_m_mma(int slab) {
    __shared__ __align__(16) unsigned short Ahi[2][128 * A_LD], Alo[2][128 * A_LD];
    __shared__ __align__(16) unsigned short Bhi[2][16 * B_LD],  Blo[2][16 * B_LD];
    int tid = threadIdx.x, wid = tid >> 5, lane = tid & 31;
    int warp_m = wid & 3, warp_n = wid >> 2;
    int tm = blockIdx.y, tn = blockIdx.x;

    int ar = tid >> 1, ac = (tid & 1) * 8;
    int bk = tid >> 4, bc = (tid & 15) * 8;

    float c[2][8][4];
#pragma unroll
    for (int i = 0; i < 2; i++)
#pragma unroll
        for (int j = 0; j < 8; j++)
#pragma unroll
            for (int q = 0; q < 4; q++) c[i][j][q] = 0.f;

#define STAGE_M(s, kc) { \
    size_t asrc = (size_t)(slab * SLAB + tm * 128 + ar) * DIMV + (kc) * 16 + ac; \
    cpa16(&Ahi[s][ar * A_LD + ac], g_x_hi + asrc); \
    cpa16(&Alo[s][ar * A_LD + ac], g_x_lo + asrc); \
    size_t bsrc = (size_t)((kc) * 16 + bk) * W2N + tn * 128 + bc; \
    cpa16(&Bhi[s][bk * B_LD + bc], g_W2T_hi + bsrc); \
    cpa16(&Blo[s][bk * B_LD + bc], g_W2T_lo + bsrc); \
    CPA_COMMIT(); }

    STAGE_M(0, 0);
    for (int kc = 0; kc < 4; kc++) {
        if (kc < 3) { STAGE_M((kc + 1) & 1, kc + 1); CPA_WAIT1(); }
        else        { CPA_WAIT0(); }
        __syncthreads();
        int b = kc & 1;
        warp_kstep(c, Ahi[b], Alo[b], Bhi[b], Blo[b], warp_m, warp_n, lane);
        __syncthreads();
    }
#undef STAGE_M

    int rbase = tm * 128 + warp_m * 32 + (lane >> 2);
    int cbase = tn * 128 + warp_n * 64 + (lane & 3) * 2;
#pragma unroll
    for (int mi = 0; mi < 2; mi++) {
#pragma unroll
        for (int n8 = 0; n8 < 8; n8++) {
            int col = cbase + n8 * 8;
            int r0 = rbase + mi * 16;
            if (r0 < SLAB)
                *(float2*)&g_M[(size_t)r0 * W2N + col] = make_float2(c[mi][n8][0], c[mi][n8][1]);
            int r1 = r0 + 8;
            if (r1 < SLAB)
                *(float2*)&g_M[(size_t)r1 * W2N + col] = make_float2(c[mi][n8][2], c[mi][n8][3]);
        }
    }
}

// ---------------- generic tiled SGEMM (FFMA2): small GEMMs ----------------
template <bool RELU>
__global__ void __launch_bounds__(256, 2)
sgemm(const float* __restrict__ A, const float* __restrict__ B,
      const float* __restrict__ bias, float* __restrict__ C,
      int M, int N, int K) {
    __shared__ __align__(16) float As[16][132];
    __shared__ __align__(16) float Bs[16][128];
    int bm = blockIdx.y * 128, bn = blockIdx.x * 128;
    int tid = threadIdx.x;
    int tr = tid >> 4, tc = tid & 15;
    bool k4 = ((K & 3) == 0);

    u64t acc2[8][4];
#pragma unroll
    for (int i = 0; i < 8; i++)
#pragma unroll
        for (int j = 0; j < 4; j++) acc2[i][j] = 0ull;

    for (int kt = 0; kt < K; kt += 16) {
#pragma unroll
        for (int l = 0; l < 2; l++) {
            int lin = tid + l * 256;
            int row = lin >> 2;
            int kq  = (lin & 3) * 4;
            float4 v = make_float4(0.f, 0.f, 0.f, 0.f);
            int gr = bm + row;
            if (gr < M) {
                int k0 = kt + kq;
                if (k4 && k0 + 3 < K) {
                    v = *(const float4*)&A[(size_t)gr * K + k0];
                } else {
                    float t0[4] = {0.f, 0.f, 0.f, 0.f};
#pragma unroll
                    for (int i = 0; i < 4; i++)
                        if (k0 + i < K) t0[i] = A[(size_t)gr * K + k0 + i];
                    v = make_float4(t0[0], t0[1], t0[2], t0[3]);
                }
            }
            As[kq + 0][row] = v.x; As[kq + 1][row] = v.y;
            As[kq + 2][row] = v.z; As[kq + 3][row] = v.w;
        }
#pragma unroll
        for (int l = 0; l < 2; l++) {
            int lin = tid + l * 256;
            int kr = lin >> 5;
            int nq = (lin & 31) * 4;
            float4 v = make_float4(0.f, 0.f, 0.f, 0.f);
            int gk = kt + kr, gn = bn + nq;
            if (gk < K && gn + 3 < N)
                v = *(const float4*)&B[(size_t)gk * N + gn];
            *(float4*)&Bs[kr][nq] = v;
        }
        __syncthreads();
#pragma unroll
        for (int k = 0; k < 16; k++) {
            float a[8];
            *(float4*)&a[0] = *(const float4*)&As[k][tr * 8];
            *(float4*)&a[4] = *(const float4*)&As[k][tr * 8 + 4];
            u64t b2[4];
            const u64t* bp = (const u64t*)&Bs[k][tc * 8];
            b2[0] = bp[0]; b2[1] = bp[1]; b2[2] = bp[2]; b2[3] = bp[3];
#pragma unroll
            for (int i = 0; i < 8; i++) {
                u64t ad = pack_dup(a[i]);
#pragma unroll
                for (int j = 0; j < 4; j++) fma2(acc2[i][j], ad, b2[j]);
            }
        }
        __syncthreads();
    }
#pragma unroll
    for (int i = 0; i < 8; i++) {
        int gr = bm + tr * 8 + i;
        if (gr >= M) continue;
#pragma unroll
        for (int j = 0; j < 4; j++) {
            float2 p = *(float2*)&acc2[i][j];
            int gn0 = bn + tc * 8 + 2 * j;
#pragma unroll
            for (int s = 0; s < 2; s++) {
                int gn = gn0 + s;
                if (gn >= N) continue;
                float v = (s == 0) ? p.x : p.y;
                if (bias) v += bias[gn];
                if (RELU) v = fmaxf(v, 0.f);
                C[(size_t)gr * N + gn] = v;
            }
        }
    }
}

// ---------------- attention path ----------------
__global__ void score_kernel(const int* __restrict__ ei_mf, const float* __restrict__ ea_mf,
                             const float* __restrict__ We) {
    __shared__ float sWe[6 * 64];
    int tid = threadIdx.x;
    for (int i = tid; i < 6 * 64; i += blockDim.x) sWe[i] = We[i];
    __syncthreads();
    int e = blockIdx.x * 8 + (tid >> 5);
    if (e >= EMFN) return;
    int l = tid & 31;
    int src = ei_mf[e];
    int dst = ei_mf[EMFN + e];
    float ke0 = g_kk[src * 64 + l];
    float ke1 = g_kk[src * 64 + 32 + l];
#pragma unroll
    for (int j = 0; j < 6; j++) {
        float ea = ea_mf[e * 6 + j];
        ke0 = fmaf(ea, sWe[j * 64 + l], ke0);
        ke1 = fmaf(ea, sWe[j * 64 + 32 + l], ke1);
    }
    float s = g_q[dst * 64 + l] * ke0 + g_q[dst * 64 + 32 + l] * ke1;
#pragma unroll
    for (int off = 16; off; off >>= 1) s += __shfl_down_sync(0xffffffffu, s, off);
    if (l == 0) {
        s *= 0.125f;
        g_score[e] = s;
        atomicMax(&g_mkey[dst], kenc(s));
    }
}

__global__ void exp_kernel(const int* __restrict__ ei_mf) {
    int e = blockIdx.x * blockDim.x + threadIdx.x;
    if (e >= EMFN) return;
    int dst = ei_mf[EMFN + e];
    float a = expf(g_score[e] - kdec(g_mkey[dst]));
    g_av[e] = a;
    atomicAdd(&g_z[dst], a);
}

__global__ void xcacc_kernel(const int* __restrict__ ei_mf) {
    int e = blockIdx.x * 8 + (threadIdx.x >> 5);
    if (e >= EMFN) return;
    int l = threadIdx.x & 31;
    int src = ei_mf[e];
    int dst = ei_mf[EMFN + e];
    float alpha = g_av[e] / (g_z[dst] + 1e-9f);
    atomicAdd(&g_xc[dst * 64 + l],      alpha * g_v[src * 64 + l]);
    atomicAdd(&g_xc[dst * 64 + 32 + l], alpha * g_v[src * 64 + 32 + l]);
}

__global__ void dual64_kernel(const float* __restrict__ x, const float* __restrict__ Wroot,
                              const float* __restrict__ broot, const float* __restrict__ Wo,
                              const float* __restrict__ bo) {
    __shared__ float sWr[64 * 64], sWo[64 * 64], sx[4][64], sxc[4][64];
    int tid = threadIdx.x;
    for (int i = tid; i < 4096; i += 256) { sWr[i] = Wroot[i]; sWo[i] = Wo[i]; }
    int r0 = blockIdx.x * 4;
    {
        int rr = tid >> 6, cc = tid & 63;
        int gr = r0 + rr;
        sx[rr][cc]  = (gr < NF) ? x[gr * 64 + cc]    : 0.f;
        sxc[rr][cc] = (gr < NF) ? g_xc[gr * 64 + cc] : 0.f;
    }
    __syncthreads();
    int rr = tid >> 6, cc = tid & 63;
    int gr = r0 + rr;
    if (gr < NF) {
        float s = broot[cc] + bo[cc];
#pragma unroll 8
        for (int d = 0; d < 64; d++)
            s += sx[rr][d] * sWr[d * 64 + cc] + sxc[rr][d] * sWo[d * 64 + cc];
        g_base[gr * 64 + cc] = s;
    }
}

// ---------------- CSR by src over ff-edges ----------------
__global__ void cnt_kernel(const int* __restrict__ ei_ff) {
    int e = blockIdx.x * blockDim.x + threadIdx.x;
    if (e < EFFN) atomicAdd(&g_cnt[ei_ff[e]], 1);
}

__global__ void scan_kernel() {
    __shared__ int s[1024];
    __shared__ int carry;
    int tid = threadIdx.x;
    if (tid == 0) carry = 0;
    __syncthreads();
    for (int base = 0; base < NF; base += 1024) {
        int i = base + tid;
        int v = (i < NF) ? g_cnt[i] : 0;
        s[tid] = v;
        __syncthreads();
        for (int off = 1; off < 1024; off <<= 1) {
            int t = (tid >= off) ? s[tid - off] : 0;
            __syncthreads();
            s[tid] += t;
            __syncthreads();
        }
        if (i < NF) { int ex = carry + s[tid] - v; g_off[i] = ex; g_pos[i] = ex; }
        __syncthreads();
        if (tid == 0) carry += s[1023];
        __syncthreads();
    }
    if (tid == 0) g_off[NF] = carry;
}

__global__ void fill_kernel(const int* __restrict__ ei_ff) {
    int e = blockIdx.x * blockDim.x + threadIdx.x;
    if (e < EFFN) {
        int p = atomicAdd(&g_pos[ei_ff[e]], 1);
        g_perm[p] = e;
    }
}

// ---------------- phase B: per-node msg = h[e] @ M[node] -> atomic aggr[dst] ----------------
__global__ void __launch_bounds__(256)
msg_kernel(const int* __restrict__ ei_ff, int slab) {
    __shared__ __align__(16) float Ms[128][64];
    __shared__ __align__(16) float hs[8][128];
    __shared__ float red[8][4][64];
    int tid = threadIdx.x;
    int nl = blockIdx.x;
    int n  = slab * SLAB + nl;
    int begin = g_off[n], end = g_off[n + 1];
    if (begin == end) return;
    int f = tid & 63, slice = tid >> 6;
    const float* Mrow = g_M + (size_t)nl * W2N;
    float cbias = g_c[n * 64 + f];

    for (int e0 = begin; e0 < end; e0 += 8) {
        int ec = min(8, end - e0);
        u64t acc2[8];
#pragma unroll
        for (int j = 0; j < 8; j++) acc2[j] = 0ull;

        for (int kt = 0; kt < 4; kt++) {
#pragma unroll
            for (int l = 0; l < 8; l++) {
                int lin = tid + l * 256;
                int k = lin >> 4;
                int fq = (lin & 15) * 4;
                *(float4*)&Ms[k][fq] = *(const float4*)&Mrow[(kt * 128 + k) * 64 + fq];
            }
            {
                int j  = tid >> 5;
                int kq = (tid & 31) * 4;
                float4 v = make_float4(0.f, 0.f, 0.f, 0.f);
                if (j < ec) {
                    int e = g_perm[e0 + j];
                    v = *(const float4*)&g_h[(size_t)e * KWN + kt * 128 + kq];
                }
                *(float4*)&hs[j][kq] = v;
            }
            __syncthreads();
#pragma unroll
            for (int kk2 = 0; kk2 < 16; kk2++) {
                int k = slice * 32 + kk2 * 2;
                u64t m2 = pack2(Ms[k][f], Ms[k + 1][f]);
#pragma unroll
                for (int j = 0; j < 8; j++) {
                    u64t h2 = *(const u64t*)&hs[j][k];
                    fma2(acc2[j], h2, m2);
                }
            }
            __syncthreads();
        }
        for (int j = 0; j < ec; j++) {
            float2 p = *(float2*)&acc2[j];
            red[j][slice][f] = p.x + p.y;
        }
        __syncthreads();
        for (int jb = 0; jb < ec; jb += 4) {
            int j = jb + (tid >> 6);
            if (j < ec) {
                float s = red[j][0][f] + red[j][1][f] + red[j][2][f] + red[j][3][f] + cbias;
                int e = g_perm[e0 + j];
                int dst = ei_ff[EFFN + e];
                atomicAdd(&g_aggr[dst * 64 + f], s);
            }
        }
        __syncthreads();
    }
}

// ---------------- FiLM epilogue ----------------
__global__ void ss_kernel(const float* __restrict__ tau, const float* __restrict__ Wt1,
                          const float* __restrict__ bt1, const float* __restrict__ Wt2,
                          const float* __restrict__ bt2) {
    __shared__ float temb[64];
    int tid = threadIdx.x;
    if (tid < 64) temb[tid] = silu(tau[0] * Wt1[tid] + bt1[tid]);
    __syncthreads();
    if (tid < 128) {
        float s = bt2[tid];
        for (int d = 0; d < 64; d++) s += temb[d] * Wt2[d * 128 + tid];
        g_ss[tid] = s;
    }
}

__global__ void final_kernel(float* __restrict__ out) {
    int idx = blockIdx.x * blockDim.x + threadIdx.x;
    if (idx >= NF * 64) return;
    int fcol = idx & 63;
    float g = g_base[idx] + g_aggr[idx];
    g = fmaxf(g, 0.f);
    float y = g * (1.f + g_ss[fcol]) + g_ss[64 + fcol];
    out[idx] = silu(y);
}

// ---------------- host ----------------
extern "C" void kernel_launch(void* const* d_in, const int* in_sizes, int n_in,
                              void* d_out, int out_size) {
    const float* x_flow = (const float*)d_in[0];
    const float* x_memb = (const float*)d_in[1];
    const int *ei_ff, *ei_mf;
    const float *ea_ff, *ea_mf, *tau;
    if (in_sizes[2] == 2 * EFFN) {
        ei_ff = (const int*)d_in[2];  ea_ff = (const float*)d_in[3];
        ei_mf = (const int*)d_in[4];  ea_mf = (const float*)d_in[5];
        tau   = (const float*)d_in[6];
    } else {
        ea_ff = (const float*)d_in[2]; ea_mf = (const float*)d_in[3];
        tau   = (const float*)d_in[4];
        ei_ff = (const int*)d_in[5];   ei_mf = (const int*)d_in[6];
    }
    const float* Wk0   = (const float*)d_in[7];
    const float* bk0   = (const float*)d_in[8];
    const float* Wk1   = (const float*)d_in[9];
    const float* bk1   = (const float*)d_in[10];
    const float* Wk2   = (const float*)d_in[11];
    const float* bk2   = (const float*)d_in[12];
    const float* Wroot = (const float*)d_in[13];
    const float* broot = (const float*)d_in[14];
    const float* Wq    = (const float*)d_in[15];
    const float* Wkk   = (const float*)d_in[16];
    const float* Wv    = (const float*)d_in[17];
    const float* We    = (const float*)d_in[18];
    const float* Wo    = (const float*)d_in[19];
    const float* bo    = (const float*)d_in[20];
    const float* Wt1   = (const float*)d_in[21];
    const float* bt1   = (const float*)d_in[22];
    const float* Wt2   = (const float*)d_in[23];
    const float* bt2   = (const float*)d_in[24];
    float* out = (float*)d_out;

    unsigned *p_mkey; float *p_z, *p_xc, *p_aggr; int* p_cnt;
    cudaGetSymbolAddress((void**)&p_mkey, g_mkey);
    cudaGetSymbolAddress((void**)&p_z,    g_z);
    cudaGetSymbolAddress((void**)&p_xc,   g_xc);
    cudaGetSymbolAddress((void**)&p_aggr, g_aggr);
    cudaGetSymbolAddress((void**)&p_cnt,  g_cnt);
    float *p_q, *p_kk, *p_v, *p_c;
    cudaGetSymbolAddress((void**)&p_q,   g_q);
    cudaGetSymbolAddress((void**)&p_kk,  g_kk);
    cudaGetSymbolAddress((void**)&p_v,   g_v);
    cudaGetSymbolAddress((void**)&p_c,   g_c);

    // -- ordered so profiler -s 5 -c 1 lands on a GEMM --
    conv_w2t<<<(DIMV * W2N + 255) / 256, 256>>>(Wk2);                 // 0
    conv_wk1<<<(KWN * KWN + 255) / 256, 256>>>(Wk1);                  // 1
    conv_x<<<(NF * DIMV + 255) / 256, 256>>>(x_flow);                 // 2
    h0_split<<<EFFN / 8, 256>>>(ea_ff, Wk0, bk0);                     // 3
    gemm_h_mma<<<dim3(4, (EFFN + 127) / 128), 256>>>(bk1);            // 4
    gemm_m_mma<<<dim3(W2N / 128, 4), 256>>>(0);                       // 5

    // init zeros
    zero_u32<<<160, 256>>>(p_mkey, NF);
    zero_u32<<<160, 256>>>((unsigned*)p_z, NF);
    zero_u32<<<640, 256>>>((unsigned*)p_xc, NF * 64);
    zero_u32<<<640, 256>>>((unsigned*)p_aggr, NF * 64);
    zero_u32<<<160, 256>>>((unsigned*)p_cnt, NF);

    // small GEMMs: q, k, v, c
    {
        dim3 g1(1, (NF + 127) / 128);
        sgemm<false><<<g1, 256>>>(x_flow, Wq, nullptr, p_q, NF, 64, 64);
        dim3 g2(1, (NMB + 127) / 128);
        sgemm<false><<<g2, 256>>>(x_memb, Wkk, nullptr, p_kk, NMB, 64, 64);
        sgemm<false><<<g2, 256>>>(x_memb, Wv, nullptr, p_v, NMB, 64, 64);
        sgemm<false><<<g1, 256>>>(x_flow, bk2, nullptr, p_c, NF, 64, 64);
    }

    // attention path
    score_kernel<<<(EMFN + 7) / 8, 256>>>(ei_mf, ea_mf, We);
    exp_kernel<<<(EMFN + 255) / 256, 256>>>(ei_mf);
    xcacc_kernel<<<(EMFN + 7) / 8, 256>>>(ei_mf);
    dual64_kernel<<<(NF + 3) / 4, 256>>>(x_flow, Wroot, broot, Wo, bo);

    // CSR by src
    cnt_kernel<<<(EFFN + 255) / 256, 256>>>(ei_ff);
    scan_kernel<<<1, 1024>>>();
    fill_kernel<<<(EFFN + 255) / 256, 256>>>(ei_ff);

    // slab 0 msg (gemm_m slab0 already launched above), then remaining slabs
    msg_kernel<<<SLAB, 256>>>(ei_ff, 0);
    for (int s = 1; s < NSLAB; s++) {
        gemm_m_mma<<<dim3(W2N / 128, 4), 256>>>(s);
        msg_kernel<<<SLAB, 256>>>(ei_ff, s);
    }

    // FiLM epilogue
    ss_kernel<<<1, 128>>>(tau, Wt1, bt1, Wt2, bt2);
    final_kernel<<<(NF * 64 + 255) / 256, 256>>>(out);
}

// round 14
// speedup vs baseline: 1.0672x; 1.0672x over previous
#include <cuda_runtime.h>
#include <cuda_bf16.h>
#include <math.h>
#include <stdint.h>

#define NF    20000
#define NMB   5000
#define EFFN  100000
#define EMFN  80000
#define DIMV  64
#define KWN   512
#define SLAB  500
#define NSLAB 40
#define W2N   32768            // KWN * DIMV

#define A_LD  24               // 16 k + 8 pad (ushort)
#define B_LD  136              // 128 n + 8 pad (ushort)

typedef unsigned long long u64t;

// ---------------- device scratch (__device__ globals; no allocations) ----------------
__device__ float    g_h [(size_t)EFFN * KWN];           // 204.8 MB
__device__ float    g_M [(size_t)SLAB * W2N];           // 65.5 MB
__device__ unsigned short g_W2T_hi[(size_t)DIMV * W2N]; // 4 MB  [d][n=k*64+f]
__device__ unsigned short g_W2T_lo[(size_t)DIMV * W2N];
__device__ unsigned short g_Wk1_hi[KWN * KWN];          // 512 KB [k][n]
__device__ unsigned short g_Wk1_lo[KWN * KWN];
__device__ float    g_q [NF * DIMV];
__device__ float    g_kk[NMB * DIMV];
__device__ float    g_v [NMB * DIMV];
__device__ float    g_c [NF * DIMV];
__device__ float    g_score[EMFN];
__device__ float    g_av[EMFN];
__device__ unsigned g_mkey[NF];
__device__ float    g_z[NF];
__device__ float    g_xc[NF * DIMV];
__device__ float    g_base[NF * DIMV];
__device__ float    g_aggr[NF * DIMV];
__device__ int      g_cnt[NF];
__device__ int      g_off[NF + 1];
__device__ int      g_pos[NF];
__device__ int      g_perm[EFFN];
__device__ float    g_ss[2 * DIMV];

// ---------------- helpers ----------------
__device__ __forceinline__ unsigned kenc(float f) {
    unsigned b = __float_as_uint(f);
    return (b & 0x80000000u) ? ~b : (b | 0x80000000u);
}
__device__ __forceinline__ float kdec(unsigned u) {
    return (u & 0x80000000u) ? __uint_as_float(u ^ 0x80000000u) : __uint_as_float(~u);
}
__device__ __forceinline__ float silu(float y) { return y / (1.f + expf(-y)); }

__device__ __forceinline__ u64t pack_dup(float x) {
    u64t r; asm("mov.b64 %0, {%1, %1};" : "=l"(r) : "r"(__float_as_uint(x))); return r;
}
__device__ __forceinline__ u64t pack2(float lo, float hi) {
    u64t r; asm("mov.b64 %0, {%1, %2};" : "=l"(r) : "r"(__float_as_uint(lo)), "r"(__float_as_uint(hi))); return r;
}
__device__ __forceinline__ void fma2(u64t& d, u64t a, u64t b) {
    asm("fma.rn.f32x2 %0, %1, %2, %0;" : "+l"(d) : "l"(a), "l"(b));
}

__device__ __forceinline__ uint32_t smem_u32(const void* p) {
    uint32_t a;
    asm("{ .reg .u64 t; cvta.to.shared.u64 t, %1; cvt.u32.u64 %0, t; }" : "=r"(a) : "l"(p));
    return a;
}
__device__ __forceinline__ void ldsm4(uint32_t& r0, uint32_t& r1, uint32_t& r2, uint32_t& r3, uint32_t a) {
    asm volatile("ldmatrix.sync.aligned.m8n8.x4.shared.b16 {%0,%1,%2,%3}, [%4];"
        : "=r"(r0), "=r"(r1), "=r"(r2), "=r"(r3) : "r"(a));
}
__device__ __forceinline__ void ldsm4t(uint32_t& r0, uint32_t& r1, uint32_t& r2, uint32_t& r3, uint32_t a) {
    asm volatile("ldmatrix.sync.aligned.m8n8.x4.trans.shared.b16 {%0,%1,%2,%3}, [%4];"
        : "=r"(r0), "=r"(r1), "=r"(r2), "=r"(r3) : "r"(a));
}
__device__ __forceinline__ void mma_bf16(float* c, const uint32_t* a, uint32_t b0, uint32_t b1) {
    asm volatile(
        "mma.sync.aligned.m16n8k16.row.col.f32.bf16.bf16.f32 "
        "{%0,%1,%2,%3}, {%4,%5,%6,%7}, {%8,%9}, {%0,%1,%2,%3};"
        : "+f"(c[0]), "+f"(c[1]), "+f"(c[2]), "+f"(c[3])
        : "r"(a[0]), "r"(a[1]), "r"(a[2]), "r"(a[3]), "r"(b0), "r"(b1));
}

// hi/lo split of 8 consecutive floats -> two 16B packets
__device__ __forceinline__ void split8(const float* s, uint4& hi, uint4& lo) {
    unsigned short h[8], l[8];
#pragma unroll
    for (int i = 0; i < 8; i++) {
        float f = s[i];
        __nv_bfloat16 bh = __float2bfloat16_rn(f);
        __nv_bfloat16 bl = __float2bfloat16_rn(f - __bfloat162float(bh));
        h[i] = __bfloat16_as_ushort(bh);
        l[i] = __bfloat16_as_ushort(bl);
    }
    hi.x = h[0] | ((unsigned)h[1] << 16); hi.y = h[2] | ((unsigned)h[3] << 16);
    hi.z = h[4] | ((unsigned)h[5] << 16); hi.w = h[6] | ((unsigned)h[7] << 16);
    lo.x = l[0] | ((unsigned)l[1] << 16); lo.y = l[2] | ((unsigned)l[3] << 16);
    lo.z = l[4] | ((unsigned)l[5] << 16); lo.w = l[6] | ((unsigned)l[7] << 16);
}

// warp-tile kstep: c[2][8][4] += bf16x3( A[32x16] , B[16x64] )
__device__ __forceinline__ void warp_kstep(float c[2][8][4],
        const unsigned short* Ahi, const unsigned short* Alo,
        const unsigned short* Bhi, const unsigned short* Blo,
        int warp_m, int warp_n, int lane) {
    int arow = lane & 15;
    int acol = (lane >> 4) << 3;
    uint32_t ahi[2][4], alo[2][4];
#pragma unroll
    for (int mi = 0; mi < 2; mi++) {
        int r = warp_m * 32 + mi * 16 + arow;
        ldsm4(ahi[mi][0], ahi[mi][1], ahi[mi][2], ahi[mi][3], smem_u32(Ahi + r * A_LD + acol));
        ldsm4(alo[mi][0], alo[mi][1], alo[mi][2], alo[mi][3], smem_u32(Alo + r * A_LD + acol));
    }
#pragma unroll
    for (int nh = 0; nh < 2; nh++) {
        uint32_t bhi[2][4], blo[2][4];
#pragma unroll
        for (int ni = 0; ni < 2; ni++) {
            int ncol = warp_n * 64 + nh * 32 + ni * 16 + acol;
            ldsm4t(bhi[ni][0], bhi[ni][1], bhi[ni][2], bhi[ni][3], smem_u32(Bhi + arow * B_LD + ncol));
            ldsm4t(blo[ni][0], blo[ni][1], blo[ni][2], blo[ni][3], smem_u32(Blo + arow * B_LD + ncol));
        }
#pragma unroll
        for (int mi = 0; mi < 2; mi++)
#pragma unroll
            for (int ni = 0; ni < 2; ni++) {
                int n8 = nh * 4 + ni * 2;
                mma_bf16(c[mi][n8],     ahi[mi], bhi[ni][0], bhi[ni][1]);
                mma_bf16(c[mi][n8 + 1], ahi[mi], bhi[ni][2], bhi[ni][3]);
                mma_bf16(c[mi][n8],     ahi[mi], blo[ni][0], blo[ni][1]);
                mma_bf16(c[mi][n8 + 1], ahi[mi], blo[ni][2], blo[ni][3]);
                mma_bf16(c[mi][n8],     alo[mi], bhi[ni][0], bhi[ni][1]);
                mma_bf16(c[mi][n8 + 1], alo[mi], bhi[ni][2], bhi[ni][3]);
            }
    }
}

// ---------------- tiny utility kernels ----------------
__global__ void zero_u32(unsigned* p, int n) {
    for (int i = blockIdx.x * blockDim.x + threadIdx.x; i < n; i += gridDim.x * blockDim.x)
        p[i] = 0u;
}

// Wk1 [k][n] -> hi/lo
__global__ void conv_wk1(const float* __restrict__ Wk1) {
    int idx = blockIdx.x * blockDim.x + threadIdx.x;
    if (idx >= KWN * KWN) return;
    float v = Wk1[idx];
    __nv_bfloat16 bh = __float2bfloat16_rn(v);
    __nv_bfloat16 bl = __float2bfloat16_rn(v - __bfloat162float(bh));
    g_Wk1_hi[idx] = __bfloat16_as_ushort(bh);
    g_Wk1_lo[idx] = __bfloat16_as_ushort(bl);
}

// W2T[d][n=k*64+f] = Wk2[k*4096 + d*64 + f] -> hi/lo
__global__ void conv_w2t(const float* __restrict__ Wk2) {
    int idx = blockIdx.x * blockDim.x + threadIdx.x;
    if (idx >= DIMV * W2N) return;
    int d = idx >> 15;
    int r = idx & 32767;
    int k = r >> 6;
    int f = r & 63;
    float v = Wk2[k * 4096 + d * 64 + f];
    __nv_bfloat16 bh = __float2bfloat16_rn(v);
    __nv_bfloat16 bl = __float2bfloat16_rn(v - __bfloat162float(bh));
    g_W2T_hi[idx] = __bfloat16_as_ushort(bh);
    g_W2T_lo[idx] = __bfloat16_as_ushort(bl);
}

// ---------------- HMMA GEMM 1 (fused h0): h = relu(relu(ea@Wk0+bk0) @ Wk1 + bk1) ----------------
__global__ void __launch_bounds__(256)
gemm_h_mma(const float* __restrict__ ea_ff, const float* __restrict__ Wk0,
           const float* __restrict__ bk0, const float* __restrict__ bk1) {
    __shared__ __align__(16) unsigned short Ahi[128 * A_LD], Alo[128 * A_LD];
    __shared__ __align__(16) unsigned short Bhi[16 * B_LD],  Blo[16 * B_LD];
    __shared__ float sWk0[6 * KWN];   // 12 KB
    __shared__ float sbk0[KWN];       // 2 KB
    int tid = threadIdx.x, wid = tid >> 5, lane = tid & 31;
    int warp_m = wid & 3, warp_n = wid >> 2;
    int tm = blockIdx.y, tn = blockIdx.x;

    // preload Wk0 + bk0 into smem (once per block)
    for (int i = tid; i < 6 * KWN; i += 256) sWk0[i] = Wk0[i];
    for (int i = tid; i < KWN; i += 256) sbk0[i] = bk0[i];

    // per-thread A-row edge features (row shared by 2 threads)
    int arow_g = tm * 128 + (tid >> 1);
    float a6[6];
    {
        bool valid = arow_g < EFFN;
        const float* ea = ea_ff + (size_t)(valid ? arow_g : 0) * 6;
#pragma unroll
        for (int j = 0; j < 6; j++) a6[j] = valid ? ea[j] : 0.f;
    }
    __syncthreads();

    int ar = tid >> 1, ac = (tid & 1) * 8;
    int bkr = tid >> 4, bc = (tid & 15) * 8;

    float c[2][8][4];
#pragma unroll
    for (int i = 0; i < 2; i++)
#pragma unroll
        for (int j = 0; j < 8; j++)
#pragma unroll
            for (int q = 0; q < 4; q++) c[i][j][q] = 0.f;

    for (int kc = 0; kc < 32; kc++) {
        // stage A: compute h0 tile on the fly (smem-broadcast Wk0)
        {
            float v[8];
#pragma unroll
            for (int i = 0; i < 8; i++) {
                int k = kc * 16 + ac + i;
                float s = sbk0[k];
#pragma unroll
                for (int j = 0; j < 6; j++) s = fmaf(a6[j], sWk0[j * KWN + k], s);
                v[i] = fmaxf(s, 0.f);
            }
            uint4 hi, lo;
            split8(v, hi, lo);
            *(uint4*)&Ahi[ar * A_LD + ac] = hi;
            *(uint4*)&Alo[ar * A_LD + ac] = lo;
        }
        // stage B: 16x128 from preconverted Wk1 (coalesced uint4)
        {
            size_t src = (size_t)(kc * 16 + bkr) * KWN + tn * 128 + bc;
            *(uint4*)&Bhi[bkr * B_LD + bc] = *(const uint4*)&g_Wk1_hi[src];
            *(uint4*)&Blo[bkr * B_LD + bc] = *(const uint4*)&g_Wk1_lo[src];
        }
        __syncthreads();
        warp_kstep(c, Ahi, Alo, Bhi, Blo, warp_m, warp_n, lane);
        __syncthreads();
    }

    // epilogue: bias + relu, direct float2 stores
    int rbase = tm * 128 + warp_m * 32 + (lane >> 2);
    int cbase = tn * 128 + warp_n * 64 + (lane & 3) * 2;
#pragma unroll
    for (int mi = 0; mi < 2; mi++) {
#pragma unroll
        for (int n8 = 0; n8 < 8; n8++) {
            int col = cbase + n8 * 8;
            float b0 = bk1[col], b1 = bk1[col + 1];
            int r0 = rbase + mi * 16;
            if (r0 < EFFN) {
                float2 v = make_float2(fmaxf(c[mi][n8][0] + b0, 0.f), fmaxf(c[mi][n8][1] + b1, 0.f));
                *(float2*)&g_h[(size_t)r0 * KWN + col] = v;
            }
            int r1 = r0 + 8;
            if (r1 < EFFN) {
                float2 v = make_float2(fmaxf(c[mi][n8][2] + b0, 0.f), fmaxf(c[mi][n8][3] + b1, 0.f));
                *(float2*)&g_h[(size_t)r1 * KWN + col] = v;
            }
        }
    }
}

// ---------------- HMMA GEMM 2: M_slab = x_slab @ W2T  [500 x 32768], K=64 ----------------
__global__ void __launch_bounds__(256)
gemm_m_mma(const float* __restrict__ x_flow, int slab) {
    __shared__ __align__(16) unsigned short Ahi[128 * A_LD], Alo[128 * A_LD];
    __shared__ __align__(16) unsigned short Bhi[16 * B_LD],  Blo[16 * B_LD];
    int tid = threadIdx.x, wid = tid >> 5, lane = tid & 31;
    int warp_m = wid & 3, warp_n = wid >> 2;
    int tm = blockIdx.y, tn = blockIdx.x;

    float c[2][8][4];
#pragma unroll
    for (int i = 0; i < 2; i++)
#pragma unroll
        for (int j = 0; j < 8; j++)
#pragma unroll
            for (int q = 0; q < 4; q++) c[i][j][q] = 0.f;

    for (int kc = 0; kc < DIMV / 16; kc++) {
        {
            int r = tid >> 1, kq = (tid & 1) * 8;
            int rl = tm * 128 + r;
            uint4 hi, lo;
            if (rl < SLAB) {
                float buf[8];
                const float* src = x_flow + ((size_t)slab * SLAB + rl) * DIMV + kc * 16 + kq;
                *(float4*)&buf[0] = *(const float4*)src;
                *(float4*)&buf[4] = *(const float4*)(src + 4);
                split8(buf, hi, lo);
            } else { hi = make_uint4(0, 0, 0, 0); lo = hi; }
            *(uint4*)&Ahi[r * A_LD + kq] = hi;
            *(uint4*)&Alo[r * A_LD + kq] = lo;
        }
        {
            int k = tid >> 4, nq = (tid & 15) * 8;
            size_t src = (size_t)(kc * 16 + k) * W2N + tn * 128 + nq;
            *(uint4*)&Bhi[k * B_LD + nq] = *(const uint4*)&g_W2T_hi[src];
            *(uint4*)&Blo[k * B_LD + nq] = *(const uint4*)&g_W2T_lo[src];
        }
        __syncthreads();
        warp_kstep(c, Ahi, Alo, Bhi, Blo, warp_m, warp_n, lane);
        __syncthreads();
    }

    int rbase = tm * 128 + warp_m * 32 + (lane >> 2);
    int cbase = tn * 128 + warp_n * 64 + (lane & 3) * 2;
#pragma unroll
    for (int mi = 0; mi < 2; mi++) {
#pragma unroll
        for (int n8 = 0; n8 < 8; n8++) {
            int col = cbase + n8 * 8;
            int r0 = rbase + mi * 16;
            if (r0 < SLAB)
                *(float2*)&g_M[(size_t)r0 * W2N + col] = make_float2(c[mi][n8][0], c[mi][n8][1]);
            int r1 = r0 + 8;
            if (r1 < SLAB)
                *(float2*)&g_M[(size_t)r1 * W2N + col] = make_float2(c[mi][n8][2], c[mi][n8][3]);
        }
    }
}

// ---------------- generic tiled SGEMM (FFMA2): small GEMMs ----------------
template <bool RELU>
__global__ void __launch_bounds__(256, 2)
sgemm(const float* __restrict__ A, const float* __restrict__ B,
      const float* __restrict__ bias, float* __restrict__ C,
      int M, int N, int K) {
    __shared__ __align__(16) float As[16][132];
    __shared__ __align__(16) float Bs[16][128];
    int bm = blockIdx.y * 128, bn = blockIdx.x * 128;
    int tid = threadIdx.x;
    int tr = tid >> 4, tc = tid & 15;
    bool k4 = ((K & 3) == 0);

    u64t acc2[8][4];
#pragma unroll
    for (int i = 0; i < 8; i++)
#pragma unroll
        for (int j = 0; j < 4; j++) acc2[i][j] = 0ull;

    for (int kt = 0; kt < K; kt += 16) {
#pragma unroll
        for (int l = 0; l < 2; l++) {
            int lin = tid + l * 256;
            int row = lin >> 2;
            int kq  = (lin & 3) * 4;
            float4 v = make_float4(0.f, 0.f, 0.f, 0.f);
            int gr = bm + row;
            if (gr < M) {
                int k0 = kt + kq;
                if (k4 && k0 + 3 < K) {
                    v = *(const float4*)&A[(size_t)gr * K + k0];
                } else {
                    float t0[4] = {0.f, 0.f, 0.f, 0.f};
#pragma unroll
                    for (int i = 0; i < 4; i++)
                        if (k0 + i < K) t0[i] = A[(size_t)gr * K + k0 + i];
                    v = make_float4(t0[0], t0[1], t0[2], t0[3]);
                }
            }
            As[kq + 0][row] = v.x; As[kq + 1][row] = v.y;
            As[kq + 2][row] = v.z; As[kq + 3][row] = v.w;
        }
#pragma unroll
        for (int l = 0; l < 2; l++) {
            int lin = tid + l * 256;
            int kr = lin >> 5;
            int nq = (lin & 31) * 4;
            float4 v = make_float4(0.f, 0.f, 0.f, 0.f);
            int gk = kt + kr, gn = bn + nq;
            if (gk < K && gn + 3 < N)
                v = *(const float4*)&B[(size_t)gk * N + gn];
            *(float4*)&Bs[kr][nq] = v;
        }
        __syncthreads();
#pragma unroll
        for (int k = 0; k < 16; k++) {
            float a[8];
            *(float4*)&a[0] = *(const float4*)&As[k][tr * 8];
            *(float4*)&a[4] = *(const float4*)&As[k][tr * 8 + 4];
            u64t b2[4];
            const u64t* bp = (const u64t*)&Bs[k][tc * 8];
            b2[0] = bp[0]; b2[1] = bp[1]; b2[2] = bp[2]; b2[3] = bp[3];
#pragma unroll
            for (int i = 0; i < 8; i++) {
                u64t ad = pack_dup(a[i]);
#pragma unroll
                for (int j = 0; j < 4; j++) fma2(acc2[i][j], ad, b2[j]);
            }
        }
        __syncthreads();
    }
#pragma unroll
    for (int i = 0; i < 8; i++) {
        int gr = bm + tr * 8 + i;
        if (gr >= M) continue;
#pragma unroll
        for (int j = 0; j < 4; j++) {
            float2 p = *(float2*)&acc2[i][j];
            int gn0 = bn + tc * 8 + 2 * j;
#pragma unroll
            for (int s = 0; s < 2; s++) {
                int gn = gn0 + s;
                if (gn >= N) continue;
                float v = (s == 0) ? p.x : p.y;
                if (bias) v += bias[gn];
                if (RELU) v = fmaxf(v, 0.f);
                C[(size_t)gr * N + gn] = v;
            }
        }
    }
}

// ---------------- attention path ----------------
__global__ void score_kernel(const int* __restrict__ ei_mf, const float* __restrict__ ea_mf,
                             const float* __restrict__ We) {
    __shared__ float sWe[6 * 64];
    int tid = threadIdx.x;
    for (int i = tid; i < 6 * 64; i += blockDim.x) sWe[i] = We[i];
    __syncthreads();
    int e = blockIdx.x * 8 + (tid >> 5);
    if (e >= EMFN) return;
    int l = tid & 31;
    int src = ei_mf[e];
    int dst = ei_mf[EMFN + e];
    float ke0 = g_kk[src * 64 + l];
    float ke1 = g_kk[src * 64 + 32 + l];
#pragma unroll
    for (int j = 0; j < 6; j++) {
        float ea = ea_mf[e * 6 + j];
        ke0 = fmaf(ea, sWe[j * 64 + l], ke0);
        ke1 = fmaf(ea, sWe[j * 64 + 32 + l], ke1);
    }
    float s = g_q[dst * 64 + l] * ke0 + g_q[dst * 64 + 32 + l] * ke1;
#pragma unroll
    for (int off = 16; off; off >>= 1) s += __shfl_down_sync(0xffffffffu, s, off);
    if (l == 0) {
        s *= 0.125f;
        g_score[e] = s;
        atomicMax(&g_mkey[dst], kenc(s));
    }
}

__global__ void exp_kernel(const int* __restrict__ ei_mf) {
    int e = blockIdx.x * blockDim.x + threadIdx.x;
    if (e >= EMFN) return;
    int dst = ei_mf[EMFN + e];
    float a = expf(g_score[e] - kdec(g_mkey[dst]));
    g_av[e] = a;
    atomicAdd(&g_z[dst], a);
}

__global__ void xcacc_kernel(const int* __restrict__ ei_mf) {
    int e = blockIdx.x * 8 + (threadIdx.x >> 5);
    if (e >= EMFN) return;
    int l = threadIdx.x & 31;
    int src = ei_mf[e];
    int dst = ei_mf[EMFN + e];
    float alpha = g_av[e] / (g_z[dst] + 1e-9f);
    atomicAdd(&g_xc[dst * 64 + l],      alpha * g_v[src * 64 + l]);
    atomicAdd(&g_xc[dst * 64 + 32 + l], alpha * g_v[src * 64 + 32 + l]);
}

__global__ void dual64_kernel(const float* __restrict__ x, const float* __restrict__ Wroot,
                              const float* __restrict__ broot, const float* __restrict__ Wo,
                              const float* __restrict__ bo) {
    __shared__ float sWr[64 * 64], sWo[64 * 64], sx[4][64], sxc[4][64];
    int tid = threadIdx.x;
    for (int i = tid; i < 4096; i += 256) { sWr[i] = Wroot[i]; sWo[i] = Wo[i]; }
    int r0 = blockIdx.x * 4;
    {
        int rr = tid >> 6, cc = tid & 63;
        int gr = r0 + rr;
        sx[rr][cc]  = (gr < NF) ? x[gr * 64 + cc]    : 0.f;
        sxc[rr][cc] = (gr < NF) ? g_xc[gr * 64 + cc] : 0.f;
    }
    __syncthreads();
    int rr = tid >> 6, cc = tid & 63;
    int gr = r0 + rr;
    if (gr < NF) {
        float s = broot[cc] + bo[cc];
#pragma unroll 8
        for (int d = 0; d < 64; d++)
            s += sx[rr][d] * sWr[d * 64 + cc] + sxc[rr][d] * sWo[d * 64 + cc];
        g_base[gr * 64 + cc] = s;
    }
}

// ---------------- CSR by src over ff-edges ----------------
__global__ void cnt_kernel(const int* __restrict__ ei_ff) {
    int e = blockIdx.x * blockDim.x + threadIdx.x;
    if (e < EFFN) atomicAdd(&g_cnt[ei_ff[e]], 1);
}

__global__ void scan_kernel() {
    __shared__ int s[1024];
    __shared__ int carry;
    int tid = threadIdx.x;
    if (tid == 0) carry = 0;
    __syncthreads();
    for (int base = 0; base < NF; base += 1024) {
        int i = base + tid;
        int v = (i < NF) ? g_cnt[i] : 0;
        s[tid] = v;
        __syncthreads();
        for (int off = 1; off < 1024; off <<= 1) {
            int t = (tid >= off) ? s[tid - off] : 0;
            __syncthreads();
            s[tid] += t;
            __syncthreads();
        }
        if (i < NF) { int ex = carry + s[tid] - v; g_off[i] = ex; g_pos[i] = ex; }
        __syncthreads();
        if (tid == 0) carry += s[1023];
        __syncthreads();
    }
    if (tid == 0) g_off[NF] = carry;
}

__global__ void fill_kernel(const int* __restrict__ ei_ff) {
    int e = blockIdx.x * blockDim.x + threadIdx.x;
    if (e < EFFN) {
        int p = atomicAdd(&g_pos[ei_ff[e]], 1);
        g_perm[p] = e;
    }
}

// ---------------- phase B: per-node msg = h[e] @ M[node] -> atomic aggr[dst] ----------------
__global__ void __launch_bounds__(256)
msg_kernel(const int* __restrict__ ei_ff, int slab) {
    __shared__ __align__(16) float Ms[128][64];
    __shared__ __align__(16) float hs[8][128];
    __shared__ float red[8][4][64];
    int tid = threadIdx.x;
    int nl = blockIdx.x;
    int n  = slab * SLAB + nl;
    int begin = g_off[n], end = g_off[n + 1];
    if (begin == end) return;
    int f = tid & 63, slice = tid >> 6;
    const float* Mrow = g_M + (size_t)nl * W2N;
    float cbias = g_c[n * 64 + f];

    for (int e0 = begin; e0 < end; e0 += 8) {
        int ec = min(8, end - e0);
        u64t acc2[8];
#pragma unroll
        for (int j = 0; j < 8; j++) acc2[j] = 0ull;

        for (int kt = 0; kt < 4; kt++) {
#pragma unroll
            for (int l = 0; l < 8; l++) {
                int lin = tid + l * 256;
                int k = lin >> 4;
                int fq = (lin & 15) * 4;
                *(float4*)&Ms[k][fq] = *(const float4*)&Mrow[(kt * 128 + k) * 64 + fq];
            }
            {
                int j  = tid >> 5;
                int kq = (tid & 31) * 4;
                float4 v = make_float4(0.f, 0.f, 0.f, 0.f);
                if (j < ec) {
                    int e = g_perm[e0 + j];
                    v = *(const float4*)&g_h[(size_t)e * KWN + kt * 128 + kq];
                }
                *(float4*)&hs[j][kq] = v;
            }
            __syncthreads();
#pragma unroll
            for (int kk2 = 0; kk2 < 16; kk2++) {
                int k = slice * 32 + kk2 * 2;
                u64t m2 = pack2(Ms[k][f], Ms[k + 1][f]);
#pragma unroll
                for (int j = 0; j < 8; j++) {
                    u64t h2 = *(const u64t*)&hs[j][k];
                    fma2(acc2[j], h2, m2);
                }
            }
            __syncthreads();
        }
        for (int j = 0; j < ec; j++) {
            float2 p = *(float2*)&acc2[j];
            red[j][slice][f] = p.x + p.y;
        }
        __syncthreads();
        for (int jb = 0; jb < ec; jb += 4) {
            int j = jb + (tid >> 6);
            if (j < ec) {
                float s = red[j][0][f] + red[j][1][f] + red[j][2][f] + red[j][3][f] + cbias;
                int e = g_perm[e0 + j];
                int dst = ei_ff[EFFN + e];
                atomicAdd(&g_aggr[dst * 64 + f], s);
            }
        }
        __syncthreads();
    }
}

// ---------------- FiLM epilogue ----------------
__global__ void ss_kernel(const float* __restrict__ tau, const float* __restrict__ Wt1,
                          const float* __restrict__ bt1, const float* __restrict__ Wt2,
                          const float* __restrict__ bt2) {
    __shared__ float temb[64];
    int tid = threadIdx.x;
    if (tid < 64) temb[tid] = silu(tau[0] * Wt1[tid] + bt1[tid]);
    __syncthreads();
    if (tid < 128) {
        float s = bt2[tid];
        for (int d = 0; d < 64; d++) s += temb[d] * Wt2[d * 128 + tid];
        g_ss[tid] = s;
    }
}

__global__ void final_kernel(float* __restrict__ out) {
    int idx = blockIdx.x * blockDim.x + threadIdx.x;
    if (idx >= NF * 64) return;
    int fcol = idx & 63;
    float g = g_base[idx] + g_aggr[idx];
    g = fmaxf(g, 0.f);
    float y = g * (1.f + g_ss[fcol]) + g_ss[64 + fcol];
    out[idx] = silu(y);
}

// ---------------- host ----------------
extern "C" void kernel_launch(void* const* d_in, const int* in_sizes, int n_in,
                              void* d_out, int out_size) {
    const float* x_flow = (const float*)d_in[0];
    const float* x_memb = (const float*)d_in[1];
    const int *ei_ff, *ei_mf;
    const float *ea_ff, *ea_mf, *tau;
    if (in_sizes[2] == 2 * EFFN) {
        ei_ff = (const int*)d_in[2];  ea_ff = (const float*)d_in[3];
        ei_mf = (const int*)d_in[4];  ea_mf = (const float*)d_in[5];
        tau   = (const float*)d_in[6];
    } else {
        ea_ff = (const float*)d_in[2]; ea_mf = (const float*)d_in[3];
        tau   = (const float*)d_in[4];
        ei_ff = (const int*)d_in[5];   ei_mf = (const int*)d_in[6];
    }
    const float* Wk0   = (const float*)d_in[7];
    const float* bk0   = (const float*)d_in[8];
    const float* Wk1   = (const float*)d_in[9];
    const float* bk1   = (const float*)d_in[10];
    const float* Wk2   = (const float*)d_in[11];
    const float* bk2   = (const float*)d_in[12];
    const float* Wroot = (const float*)d_in[13];
    const float* broot = (const float*)d_in[14];
    const float* Wq    = (const float*)d_in[15];
    const float* Wkk   = (const float*)d_in[16];
    const float* Wv    = (const float*)d_in[17];
    const float* We    = (const float*)d_in[18];
    const float* Wo    = (const float*)d_in[19];
    const float* bo    = (const float*)d_in[20];
    const float* Wt1   = (const float*)d_in[21];
    const float* bt1   = (const float*)d_in[22];
    const float* Wt2   = (const float*)d_in[23];
    const float* bt2   = (const float*)d_in[24];
    float* out = (float*)d_out;

    unsigned *p_mkey; float *p_z, *p_xc, *p_aggr; int* p_cnt;
    cudaGetSymbolAddress((void**)&p_mkey, g_mkey);
    cudaGetSymbolAddress((void**)&p_z,    g_z);
    cudaGetSymbolAddress((void**)&p_xc,   g_xc);
    cudaGetSymbolAddress((void**)&p_aggr, g_aggr);
    cudaGetSymbolAddress((void**)&p_cnt,  g_cnt);
    float *p_q, *p_kk, *p_v, *p_c;
    cudaGetSymbolAddress((void**)&p_q,   g_q);
    cudaGetSymbolAddress((void**)&p_kk,  g_kk);
    cudaGetSymbolAddress((void**)&p_v,   g_v);
    cudaGetSymbolAddress((void**)&p_c,   g_c);

    // -- weight conversion first; gemm_h early so profiler window lands on it --
    conv_w2t<<<(DIMV * W2N + 255) / 256, 256>>>(Wk2);                 // 0
    conv_wk1<<<(KWN * KWN + 255) / 256, 256>>>(Wk1);                  // 1
    zero_u32<<<640, 256>>>((unsigned*)p_aggr, NF * 64);               // 2
    gemm_h_mma<<<dim3(4, (EFFN + 127) / 128), 256>>>(ea_ff, Wk0, bk0, bk1); // 3
    gemm_m_mma<<<dim3(W2N / 128, 4), 256>>>(x_flow, 0);               // 4

    // init zeros
    zero_u32<<<160, 256>>>(p_mkey, NF);
    zero_u32<<<160, 256>>>((unsigned*)p_z, NF);
    zero_u32<<<640, 256>>>((unsigned*)p_xc, NF * 64);
    zero_u32<<<160, 256>>>((unsigned*)p_cnt, NF);

    // small GEMMs: q, k, v, c
    {
        dim3 g1(1, (NF + 127) / 128);
        sgemm<false><<<g1, 256>>>(x_flow, Wq, nullptr, p_q, NF, 64, 64);
        dim3 g2(1, (NMB + 127) / 128);
        sgemm<false><<<g2, 256>>>(x_memb, Wkk, nullptr, p_kk, NMB, 64, 64);
        sgemm<false><<<g2, 256>>>(x_memb, Wv, nullptr, p_v, NMB, 64, 64);
        sgemm<false><<<g1, 256>>>(x_flow, bk2, nullptr, p_c, NF, 64, 64);
    }

    // attention path
    score_kernel<<<(EMFN + 7) / 8, 256>>>(ei_mf, ea_mf, We);
    exp_kernel<<<(EMFN + 255) / 256, 256>>>(ei_mf);
    xcacc_kernel<<<(EMFN + 7) / 8, 256>>>(ei_mf);
    dual64_kernel<<<(NF + 3) / 4, 256>>>(x_flow, Wroot, broot, Wo, bo);

    // CSR by src
    cnt_kernel<<<(EFFN + 255) / 256, 256>>>(ei_ff);
    scan_kernel<<<1, 1024>>>();
    fill_kernel<<<(EFFN + 255) / 256, 256>>>(ei_ff);

    // slab 0 msg (gemm_m slab0 already launched above), then remaining slabs
    msg_kernel<<<SLAB, 256>>>(ei_ff, 0);
    for (int s = 1; s < NSLAB; s++) {
        gemm_m_mma<<<dim3(W2N / 128, 4), 256>>>(x_flow, s);
        msg_kernel<<<SLAB, 256>>>(ei_ff, s);
    }

    // FiLM epilogue
    ss_kernel<<<1, 128>>>(tau, Wt1, bt1, Wt2, bt2);
    final_kernel<<<(NF * 64 + 255) / 256, 256>>>(out);
}

// round 15
// speedup vs baseline: 1.2029x; 1.1271x over previous
#include <cuda_runtime.h>
#include <cuda_bf16.h>
#include <cuda_fp16.h>
#include <math.h>
#include <stdint.h>

#define NF    20000
#define NMB   5000
#define EFFN  100000
#define EMFN  80000
#define DIMV  64
#define KWN   512
#define SLAB  500
#define NSLAB 40
#define W2N   32768            // KWN * DIMV

#define A_LD  24               // 16 k + 8 pad (ushort)
#define B_LD  136              // 128 n + 8 pad (ushort)

typedef unsigned long long u64t;

// ---------------- device scratch (__device__ globals; no allocations) ----------------
__device__ float    g_h [(size_t)EFFN * KWN];           // 204.8 MB
__device__ float    g_M [(size_t)SLAB * W2N];           // 65.5 MB
__device__ unsigned short g_W2T_h[(size_t)DIMV * W2N];  // 4 MB  fp16 [d][n=k*64+f]
__device__ unsigned short g_Wk1_h[KWN * KWN];           // 512 KB fp16 [k][n]
__device__ unsigned short g_x_hi[(NF + 512) * DIMV];    // fp16 hi
__device__ unsigned short g_x_lo[(NF + 512) * DIMV];    // fp16 lo
__device__ float    g_q [NF * DIMV];
__device__ float    g_kk[NMB * DIMV];
__device__ float    g_v [NMB * DIMV];
__device__ float    g_c [NF * DIMV];
__device__ float    g_score[EMFN];
__device__ float    g_av[EMFN];
__device__ unsigned g_mkey[NF];
__device__ float    g_z[NF];
__device__ float    g_xc[NF * DIMV];
__device__ float    g_base[NF * DIMV];
__device__ float    g_aggr[NF * DIMV];
__device__ int      g_cnt[NF];
__device__ int      g_off[NF + 1];
__device__ int      g_pos[NF];
__device__ int      g_perm[EFFN];
__device__ float    g_ss[2 * DIMV];

// ---------------- helpers ----------------
__device__ __forceinline__ unsigned kenc(float f) {
    unsigned b = __float_as_uint(f);
    return (b & 0x80000000u) ? ~b : (b | 0x80000000u);
}
__device__ __forceinline__ float kdec(unsigned u) {
    return (u & 0x80000000u) ? __uint_as_float(u ^ 0x80000000u) : __uint_as_float(~u);
}
__device__ __forceinline__ float silu(float y) { return y / (1.f + expf(-y)); }

__device__ __forceinline__ u64t pack_dup(float x) {
    u64t r; asm("mov.b64 %0, {%1, %1};" : "=l"(r) : "r"(__float_as_uint(x))); return r;
}
__device__ __forceinline__ u64t pack2(float lo, float hi) {
    u64t r; asm("mov.b64 %0, {%1, %2};" : "=l"(r) : "r"(__float_as_uint(lo)), "r"(__float_as_uint(hi))); return r;
}
__device__ __forceinline__ void fma2(u64t& d, u64t a, u64t b) {
    asm("fma.rn.f32x2 %0, %1, %2, %0;" : "+l"(d) : "l"(a), "l"(b));
}

__device__ __forceinline__ uint32_t smem_u32(const void* p) {
    uint32_t a;
    asm("{ .reg .u64 t; cvta.to.shared.u64 t, %1; cvt.u32.u64 %0, t; }" : "=r"(a) : "l"(p));
    return a;
}
__device__ __forceinline__ void ldsm4(uint32_t& r0, uint32_t& r1, uint32_t& r2, uint32_t& r3, uint32_t a) {
    asm volatile("ldmatrix.sync.aligned.m8n8.x4.shared.b16 {%0,%1,%2,%3}, [%4];"
        : "=r"(r0), "=r"(r1), "=r"(r2), "=r"(r3) : "r"(a));
}
__device__ __forceinline__ void ldsm4t(uint32_t& r0, uint32_t& r1, uint32_t& r2, uint32_t& r3, uint32_t a) {
    asm volatile("ldmatrix.sync.aligned.m8n8.x4.trans.shared.b16 {%0,%1,%2,%3}, [%4];"
        : "=r"(r0), "=r"(r1), "=r"(r2), "=r"(r3) : "r"(a));
}
__device__ __forceinline__ void mma_f16(float* c, const uint32_t* a, uint32_t b0, uint32_t b1) {
    asm volatile(
        "mma.sync.aligned.m16n8k16.row.col.f32.f16.f16.f32 "
        "{%0,%1,%2,%3}, {%4,%5,%6,%7}, {%8,%9}, {%0,%1,%2,%3};"
        : "+f"(c[0]), "+f"(c[1]), "+f"(c[2]), "+f"(c[3])
        : "r"(a[0]), "r"(a[1]), "r"(a[2]), "r"(a[3]), "r"(b0), "r"(b1));
}

// fp16 hi/lo split of 8 consecutive floats -> two 16B packets (A side, exact to ~2^-22)
__device__ __forceinline__ void split8h(const float* s, uint4& hi, uint4& lo) {
    unsigned short h[8], l[8];
#pragma unroll
    for (int i = 0; i < 8; i++) {
        float f = s[i];
        __half bh = __float2half_rn(f);
        __half bl = __float2half_rn(f - __half2float(bh));
        h[i] = __half_as_ushort(bh);
        l[i] = __half_as_ushort(bl);
    }
    hi.x = h[0] | ((unsigned)h[1] << 16); hi.y = h[2] | ((unsigned)h[3] << 16);
    hi.z = h[4] | ((unsigned)h[5] << 16); hi.w = h[6] | ((unsigned)h[7] << 16);
    lo.x = l[0] | ((unsigned)l[1] << 16); lo.y = l[2] | ((unsigned)l[3] << 16);
    lo.z = l[4] | ((unsigned)l[5] << 16); lo.w = l[6] | ((unsigned)l[7] << 16);
}

// warp-tile kstep (fp16x2): c[2][8][4] += (Ahi+Alo)[32x16] * B[16x64]
__device__ __forceinline__ void warp_kstep(float c[2][8][4],
        const unsigned short* Ahi, const unsigned short* Alo,
        const unsigned short* Bs,
        int warp_m, int warp_n, int lane) {
    int arow = lane & 15;
    int acol = (lane >> 4) << 3;
    uint32_t ahi[2][4], alo[2][4];
#pragma unroll
    for (int mi = 0; mi < 2; mi++) {
        int r = warp_m * 32 + mi * 16 + arow;
        ldsm4(ahi[mi][0], ahi[mi][1], ahi[mi][2], ahi[mi][3], smem_u32(Ahi + r * A_LD + acol));
        ldsm4(alo[mi][0], alo[mi][1], alo[mi][2], alo[mi][3], smem_u32(Alo + r * A_LD + acol));
    }
#pragma unroll
    for (int nh = 0; nh < 2; nh++) {
        uint32_t b[2][4];
#pragma unroll
        for (int ni = 0; ni < 2; ni++) {
            int ncol = warp_n * 64 + nh * 32 + ni * 16 + acol;
            ldsm4t(b[ni][0], b[ni][1], b[ni][2], b[ni][3], smem_u32(Bs + arow * B_LD + ncol));
        }
#pragma unroll
        for (int mi = 0; mi < 2; mi++)
#pragma unroll
            for (int ni = 0; ni < 2; ni++) {
                int n8 = nh * 4 + ni * 2;
                mma_f16(c[mi][n8],     ahi[mi], b[ni][0], b[ni][1]);
                mma_f16(c[mi][n8 + 1], ahi[mi], b[ni][2], b[ni][3]);
                mma_f16(c[mi][n8],     alo[mi], b[ni][0], b[ni][1]);
                mma_f16(c[mi][n8 + 1], alo[mi], b[ni][2], b[ni][3]);
            }
    }
}

// ---------------- tiny utility kernels ----------------
__global__ void zero_u32(unsigned* p, int n) {
    for (int i = blockIdx.x * blockDim.x + threadIdx.x; i < n; i += gridDim.x * blockDim.x)
        p[i] = 0u;
}

// Wk1 [k][n] -> fp16
__global__ void conv_wk1(const float* __restrict__ Wk1) {
    int idx = blockIdx.x * blockDim.x + threadIdx.x;
    if (idx >= KWN * KWN) return;
    g_Wk1_h[idx] = __half_as_ushort(__float2half_rn(Wk1[idx]));
}

// W2T[d][n=k*64+f] = Wk2[k*4096 + d*64 + f] -> fp16
__global__ void conv_w2t(const float* __restrict__ Wk2) {
    int idx = blockIdx.x * blockDim.x + threadIdx.x;
    if (idx >= DIMV * W2N) return;
    int d = idx >> 15;
    int r = idx & 32767;
    int k = r >> 6;
    int f = r & 63;
    g_W2T_h[idx] = __half_as_ushort(__float2half_rn(Wk2[k * 4096 + d * 64 + f]));
}

// x_flow -> fp16 hi/lo (A side of gemm_m, exact)
__global__ void conv_x(const float* __restrict__ x_flow) {
    int idx = blockIdx.x * blockDim.x + threadIdx.x;
    if (idx >= (NF + 512) * DIMV) return;
    float v = (idx < NF * DIMV) ? x_flow[idx] : 0.f;
    __half bh = __float2half_rn(v);
    __half bl = __float2half_rn(v - __half2float(bh));
    g_x_hi[idx] = __half_as_ushort(bh);
    g_x_lo[idx] = __half_as_ushort(bl);
}

// ---------------- HMMA GEMM 1 (fused h0): h = relu(relu(ea@Wk0+bk0) @ Wk1 + bk1) ----------------
__global__ void __launch_bounds__(256)
gemm_h_mma(const float* __restrict__ ea_ff, const float* __restrict__ Wk0,
           const float* __restrict__ bk0, const float* __restrict__ bk1) {
    __shared__ __align__(16) unsigned short Ahi[128 * A_LD], Alo[128 * A_LD];
    __shared__ __align__(16) unsigned short Bs[16 * B_LD];
    __shared__ float sWk0[6 * KWN];   // 12 KB
    __shared__ float sbk0[KWN];       // 2 KB
    int tid = threadIdx.x, wid = tid >> 5, lane = tid & 31;
    int warp_m = wid & 3, warp_n = wid >> 2;
    int tm = blockIdx.y, tn = blockIdx.x;

    for (int i = tid; i < 6 * KWN; i += 256) sWk0[i] = Wk0[i];
    for (int i = tid; i < KWN; i += 256) sbk0[i] = bk0[i];

    int arow_g = tm * 128 + (tid >> 1);
    float a6[6];
    {
        bool valid = arow_g < EFFN;
        const float* ea = ea_ff + (size_t)(valid ? arow_g : 0) * 6;
#pragma unroll
        for (int j = 0; j < 6; j++) a6[j] = valid ? ea[j] : 0.f;
    }
    __syncthreads();

    int ar = tid >> 1, ac = (tid & 1) * 8;
    int bkr = tid >> 4, bc = (tid & 15) * 8;

    float c[2][8][4];
#pragma unroll
    for (int i = 0; i < 2; i++)
#pragma unroll
        for (int j = 0; j < 8; j++)
#pragma unroll
            for (int q = 0; q < 4; q++) c[i][j][q] = 0.f;

    for (int kc = 0; kc < 32; kc++) {
        // stage A: compute h0 tile on the fly, split fp16 hi/lo
        {
            float v[8];
#pragma unroll
            for (int i = 0; i < 8; i++) {
                int k = kc * 16 + ac + i;
                float s = sbk0[k];
#pragma unroll
                for (int j = 0; j < 6; j++) s = fmaf(a6[j], sWk0[j * KWN + k], s);
                v[i] = fmaxf(s, 0.f);
            }
            uint4 hi, lo;
            split8h(v, hi, lo);
            *(uint4*)&Ahi[ar * A_LD + ac] = hi;
            *(uint4*)&Alo[ar * A_LD + ac] = lo;
        }
        // stage B: 16x128 fp16 from preconverted Wk1
        {
            size_t src = (size_t)(kc * 16 + bkr) * KWN + tn * 128 + bc;
            *(uint4*)&Bs[bkr * B_LD + bc] = *(const uint4*)&g_Wk1_h[src];
        }
        __syncthreads();
        warp_kstep(c, Ahi, Alo, Bs, warp_m, warp_n, lane);
        __syncthreads();
    }

    int rbase = tm * 128 + warp_m * 32 + (lane >> 2);
    int cbase = tn * 128 + warp_n * 64 + (lane & 3) * 2;
#pragma unroll
    for (int mi = 0; mi < 2; mi++) {
#pragma unroll
        for (int n8 = 0; n8 < 8; n8++) {
            int col = cbase + n8 * 8;
            float b0 = bk1[col], b1 = bk1[col + 1];
            int r0 = rbase + mi * 16;
            if (r0 < EFFN) {
                float2 v = make_float2(fmaxf(c[mi][n8][0] + b0, 0.f), fmaxf(c[mi][n8][1] + b1, 0.f));
                *(float2*)&g_h[(size_t)r0 * KWN + col] = v;
            }
            int r1 = r0 + 8;
            if (r1 < EFFN) {
                float2 v = make_float2(fmaxf(c[mi][n8][2] + b0, 0.f), fmaxf(c[mi][n8][3] + b1, 0.f));
                *(float2*)&g_h[(size_t)r1 * KWN + col] = v;
            }
        }
    }
}

// ---------------- HMMA GEMM 2: M_slab = x_slab @ W2T  [500 x 32768], K=64 ----------------
__global__ void __launch_bounds__(256)
gemm_m_mma(int slab) {
    __shared__ __align__(16) unsigned short Ahi[128 * A_LD], Alo[128 * A_LD];
    __shared__ __align__(16) unsigned short Bs[16 * B_LD];
    int tid = threadIdx.x, wid = tid >> 5, lane = tid & 31;
    int warp_m = wid & 3, warp_n = wid >> 2;
    int tm = blockIdx.y, tn = blockIdx.x;

    float c[2][8][4];
#pragma unroll
    for (int i = 0; i < 2; i++)
#pragma unroll
        for (int j = 0; j < 8; j++)
#pragma unroll
            for (int q = 0; q < 4; q++) c[i][j][q] = 0.f;

    int ar = tid >> 1, ac = (tid & 1) * 8;
    int bkr = tid >> 4, bc = (tid & 15) * 8;

    for (int kc = 0; kc < DIMV / 16; kc++) {
        // stage A: pure copy from precomputed fp16 hi/lo
        {
            size_t src = (size_t)(slab * SLAB + tm * 128 + ar) * DIMV + kc * 16 + ac;
            *(uint4*)&Ahi[ar * A_LD + ac] = *(const uint4*)&g_x_hi[src];
            *(uint4*)&Alo[ar * A_LD + ac] = *(const uint4*)&g_x_lo[src];
        }
        // stage B: fp16 single
        {
            size_t src = (size_t)(kc * 16 + bkr) * W2N + tn * 128 + bc;
            *(uint4*)&Bs[bkr * B_LD + bc] = *(const uint4*)&g_W2T_h[src];
        }
        __syncthreads();
        warp_kstep(c, Ahi, Alo, Bs, warp_m, warp_n, lane);
        __syncthreads();
    }

    int rbase = tm * 128 + warp_m * 32 + (lane >> 2);
    int cbase = tn * 128 + warp_n * 64 + (lane & 3) * 2;
#pragma unroll
    for (int mi = 0; mi < 2; mi++) {
#pragma unroll
        for (int n8 = 0; n8 < 8; n8++) {
            int col = cbase + n8 * 8;
            int r0 = rbase + mi * 16;
            if (r0 < SLAB)
                *(float2*)&g_M[(size_t)r0 * W2N + col] = make_float2(c[mi][n8][0], c[mi][n8][1]);
            int r1 = r0 + 8;
            if (r1 < SLAB)
                *(float2*)&g_M[(size_t)r1 * W2N + col] = make_float2(c[mi][n8][2], c[mi][n8][3]);
        }
    }
}

// ---------------- generic tiled SGEMM (FFMA2): small GEMMs ----------------
template <bool RELU>
__global__ void __launch_bounds__(256, 2)
sgemm(const float* __restrict__ A, const float* __restrict__ B,
      const float* __restrict__ bias, float* __restrict__ C,
      int M, int N, int K) {
    __shared__ __align__(16) float As[16][132];
    __shared__ __align__(16) float Bs[16][128];
    int bm = blockIdx.y * 128, bn = blockIdx.x * 128;
    int tid = threadIdx.x;
    int tr = tid >> 4, tc = tid & 15;
    bool k4 = ((K & 3) == 0);

    u64t acc2[8][4];
#pragma unroll
    for (int i = 0; i < 8; i++)
#pragma unroll
        for (int j = 0; j < 4; j++) acc2[i][j] = 0ull;

    for (int kt = 0; kt < K; kt += 16) {
#pragma unroll
        for (int l = 0; l < 2; l++) {
            int lin = tid + l * 256;
            int row = lin >> 2;
            int kq  = (lin & 3) * 4;
            float4 v = make_float4(0.f, 0.f, 0.f, 0.f);
            int gr = bm + row;
            if (gr < M) {
                int k0 = kt + kq;
                if (k4 && k0 + 3 < K) {
                    v = *(const float4*)&A[(size_t)gr * K + k0];
                } else {
                    float t0[4] = {0.f, 0.f, 0.f, 0.f};
#pragma unroll
                    for (int i = 0; i < 4; i++)
                        if (k0 + i < K) t0[i] = A[(size_t)gr * K + k0 + i];
                    v = make_float4(t0[0], t0[1], t0[2], t0[3]);
                }
            }
            As[kq + 0][row] = v.x; As[kq + 1][row] = v.y;
            As[kq + 2][row] = v.z; As[kq + 3][row] = v.w;
        }
#pragma unroll
        for (int l = 0; l < 2; l++) {
            int lin = tid + l * 256;
            int kr = lin >> 5;
            int nq = (lin & 31) * 4;
            float4 v = make_float4(0.f, 0.f, 0.f, 0.f);
            int gk = kt + kr, gn = bn + nq;
            if (gk < K && gn + 3 < N)
                v = *(const float4*)&B[(size_t)gk * N + gn];
            *(float4*)&Bs[kr][nq] = v;
        }
        __syncthreads();
#pragma unroll
        for (int k = 0; k < 16; k++) {
            float a[8];
            *(float4*)&a[0] = *(const float4*)&As[k][tr * 8];
            *(float4*)&a[4] = *(const float4*)&As[k][tr * 8 + 4];
            u64t b2[4];
            const u64t* bp = (const u64t*)&Bs[k][tc * 8];
            b2[0] = bp[0]; b2[1] = bp[1]; b2[2] = bp[2]; b2[3] = bp[3];
#pragma unroll
            for (int i = 0; i < 8; i++) {
                u64t ad = pack_dup(a[i]);
#pragma unroll
                for (int j = 0; j < 4; j++) fma2(acc2[i][j], ad, b2[j]);
            }
        }
        __syncthreads();
    }
#pragma unroll
    for (int i = 0; i < 8; i++) {
        int gr = bm + tr * 8 + i;
        if (gr >= M) continue;
#pragma unroll
        for (int j = 0; j < 4; j++) {
            float2 p = *(float2*)&acc2[i][j];
            int gn0 = bn + tc * 8 + 2 * j;
#pragma unroll
            for (int s = 0; s < 2; s++) {
                int gn = gn0 + s;
                if (gn >= N) continue;
                float v = (s == 0) ? p.x : p.y;
                if (bias) v += bias[gn];
                if (RELU) v = fmaxf(v, 0.f);
                C[(size_t)gr * N + gn] = v;
            }
        }
    }
}

// ---------------- attention path ----------------
__global__ void score_kernel(const int* __restrict__ ei_mf, const float* __restrict__ ea_mf,
                             const float* __restrict__ We) {
    __shared__ float sWe[6 * 64];
    int tid = threadIdx.x;
    for (int i = tid; i < 6 * 64; i += blockDim.x) sWe[i] = We[i];
    __syncthreads();
    int e = blockIdx.x * 8 + (tid >> 5);
    if (e >= EMFN) return;
    int l = tid & 31;
    int src = ei_mf[e];
    int dst = ei_mf[EMFN + e];
    float ke0 = g_kk[src * 64 + l];
    float ke1 = g_kk[src * 64 + 32 + l];
#pragma unroll
    for (int j = 0; j < 6; j++) {
        float ea = ea_mf[e * 6 + j];
        ke0 = fmaf(ea, sWe[j * 64 + l], ke0);
        ke1 = fmaf(ea, sWe[j * 64 + 32 + l], ke1);
    }
    float s = g_q[dst * 64 + l] * ke0 + g_q[dst * 64 + 32 + l] * ke1;
#pragma unroll
    for (int off = 16; off; off >>= 1) s += __shfl_down_sync(0xffffffffu, s, off);
    if (l == 0) {
        s *= 0.125f;
        g_score[e] = s;
        atomicMax(&g_mkey[dst], kenc(s));
    }
}

__global__ void exp_kernel(const int* __restrict__ ei_mf) {
    int e = blockIdx.x * blockDim.x + threadIdx.x;
    if (e >= EMFN) return;
    int dst = ei_mf[EMFN + e];
    float a = expf(g_score[e] - kdec(g_mkey[dst]));
    g_av[e] = a;
    atomicAdd(&g_z[dst], a);
}

__global__ void xcacc_kernel(const int* __restrict__ ei_mf) {
    int e = blockIdx.x * 8 + (threadIdx.x >> 5);
    if (e >= EMFN) return;
    int l = threadIdx.x & 31;
    int src = ei_mf[e];
    int dst = ei_mf[EMFN + e];
    float alpha = g_av[e] / (g_z[dst] + 1e-9f);
    atomicAdd(&g_xc[dst * 64 + l],      alpha * g_v[src * 64 + l]);
    atomicAdd(&g_xc[dst * 64 + 32 + l], alpha * g_v[src * 64 + 32 + l]);
}

__global__ void dual64_kernel(const float* __restrict__ x, const float* __restrict__ Wroot,
                              const float* __restrict__ broot, const float* __restrict__ Wo,
                              const float* __restrict__ bo) {
    __shared__ float sWr[64 * 64], sWo[64 * 64], sx[4][64], sxc[4][64];
    int tid = threadIdx.x;
    for (int i = tid; i < 4096; i += 256) { sWr[i] = Wroot[i]; sWo[i] = Wo[i]; }
    int r0 = blockIdx.x * 4;
    {
        int rr = tid >> 6, cc = tid & 63;
        int gr = r0 + rr;
        sx[rr][cc]  = (gr < NF) ? x[gr * 64 + cc]    : 0.f;
        sxc[rr][cc] = (gr < NF) ? g_xc[gr * 64 + cc] : 0.f;
    }
    __syncthreads();
    int rr = tid >> 6, cc = tid & 63;
    int gr = r0 + rr;
    if (gr < NF) {
        float s = broot[cc] + bo[cc];
#pragma unroll 8
        for (int d = 0; d < 64; d++)
            s += sx[rr][d] * sWr[d * 64 + cc] + sxc[rr][d] * sWo[d * 64 + cc];
        g_base[gr * 64 + cc] = s;
    }
}

// ---------------- CSR by src over ff-edges ----------------
__global__ void cnt_kernel(const int* __restrict__ ei_ff) {
    int e = blockIdx.x * blockDim.x + threadIdx.x;
    if (e < EFFN) atomicAdd(&g_cnt[ei_ff[e]], 1);
}

__global__ void scan_kernel() {
    __shared__ int s[1024];
    __shared__ int carry;
    int tid = threadIdx.x;
    if (tid == 0) carry = 0;
    __syncthreads();
    for (int base = 0; base < NF; base += 1024) {
        int i = base + tid;
        int v = (i < NF) ? g_cnt[i] : 0;
        s[tid] = v;
        __syncthreads();
        for (int off = 1; off < 1024; off <<= 1) {
            int t = (tid >= off) ? s[tid - off] : 0;
            __syncthreads();
            s[tid] += t;
            __syncthreads();
        }
        if (i < NF) { int ex = carry + s[tid] - v; g_off[i] = ex; g_pos[i] = ex; }
        __syncthreads();
        if (tid == 0) carry += s[1023];
        __syncthreads();
    }
    if (tid == 0) g_off[NF] = carry;
}

__global__ void fill_kernel(const int* __restrict__ ei_ff) {
    int e = blockIdx.x * blockDim.x + threadIdx.x;
    if (e < EFFN) {
        int p = atomicAdd(&g_pos[ei_ff[e]], 1);
        g_perm[p] = e;
    }
}

// ---------------- phase B: per-node msg = h[e] @ M[node] -> atomic aggr[dst] ----------------
__global__ void __launch_bounds__(256)
msg_kernel(const int* __restrict__ ei_ff, int slab) {
    __shared__ __align__(16) float Ms[128][64];
    __shared__ __align__(16) float hs[8][128];
    __shared__ float red[8][4][64];
    int tid = threadIdx.x;
    int nl = blockIdx.x;
    int n  = slab * SLAB + nl;
    int begin = g_off[n], end = g_off[n + 1];
    if (begin == end) return;
    int f = tid & 63, slice = tid >> 6;
    const float* Mrow = g_M + (size_t)nl * W2N;
    float cbias = g_c[n * 64 + f];

    for (int e0 = begin; e0 < end; e0 += 8) {
        int ec = min(8, end - e0);
        u64t acc2[8];
#pragma unroll
        for (int j = 0; j < 8; j++) acc2[j] = 0ull;

        for (int kt = 0; kt < 4; kt++) {
#pragma unroll
            for (int l = 0; l < 8; l++) {
                int lin = tid + l * 256;
                int k = lin >> 4;
                int fq = (lin & 15) * 4;
                *(float4*)&Ms[k][fq] = *(const float4*)&Mrow[(kt * 128 + k) * 64 + fq];
            }
            {
                int j  = tid >> 5;
                int kq = (tid & 31) * 4;
                float4 v = make_float4(0.f, 0.f, 0.f, 0.f);
                if (j < ec) {
                    int e = g_perm[e0 + j];
                    v = *(const float4*)&g_h[(size_t)e * KWN + kt * 128 + kq];
                }
                *(float4*)&hs[j][kq] = v;
            }
            __syncthreads();
#pragma unroll
            for (int kk2 = 0; kk2 < 16; kk2++) {
                int k = slice * 32 + kk2 * 2;
                u64t m2 = pack2(Ms[k][f], Ms[k + 1][f]);
#pragma unroll
                for (int j = 0; j < 8; j++) {
                    u64t h2 = *(const u64t*)&hs[j][k];
                    fma2(acc2[j], h2, m2);
                }
            }
            __syncthreads();
        }
        for (int j = 0; j < ec; j++) {
            float2 p = *(float2*)&acc2[j];
            red[j][slice][f] = p.x + p.y;
        }
        __syncthreads();
        for (int jb = 0; jb < ec; jb += 4) {
            int j = jb + (tid >> 6);
            if (j < ec) {
                float s = red[j][0][f] + red[j][1][f] + red[j][2][f] + red[j][3][f] + cbias;
                int e = g_perm[e0 + j];
                int dst = ei_ff[EFFN + e];
                atomicAdd(&g_aggr[dst * 64 + f], s);
            }
        }
        __syncthreads();
    }
}

// ---------------- FiLM epilogue ----------------
__global__ void ss_kernel(const float* __restrict__ tau, const float* __restrict__ Wt1,
                          const float* __restrict__ bt1, const float* __restrict__ Wt2,
                          const float* __restrict__ bt2) {
    __shared__ float temb[64];
    int tid = threadIdx.x;
    if (tid < 64) temb[tid] = silu(tau[0] * Wt1[tid] + bt1[tid]);
    __syncthreads();
    if (tid < 128) {
        float s = bt2[tid];
        for (int d = 0; d < 64; d++) s += temb[d] * Wt2[d * 128 + tid];
        g_ss[tid] = s;
    }
}

__global__ void final_kernel(float* __restrict__ out) {
    int idx = blockIdx.x * blockDim.x + threadIdx.x;
    if (idx >= NF * 64) return;
    int fcol = idx & 63;
    float g = g_base[idx] + g_aggr[idx];
    g = fmaxf(g, 0.f);
    float y = g * (1.f + g_ss[fcol]) + g_ss[64 + fcol];
    out[idx] = silu(y);
}

// ---------------- host ----------------
extern "C" void kernel_launch(void* const* d_in, const int* in_sizes, int n_in,
                              void* d_out, int out_size) {
    const float* x_flow = (const float*)d_in[0];
    const float* x_memb = (const float*)d_in[1];
    const int *ei_ff, *ei_mf;
    const float *ea_ff, *ea_mf, *tau;
    if (in_sizes[2] == 2 * EFFN) {
        ei_ff = (const int*)d_in[2];  ea_ff = (const float*)d_in[3];
        ei_mf = (const int*)d_in[4];  ea_mf = (const float*)d_in[5];
        tau   = (const float*)d_in[6];
    } else {
        ea_ff = (const float*)d_in[2]; ea_mf = (const float*)d_in[3];
        tau   = (const float*)d_in[4];
        ei_ff = (const int*)d_in[5];   ei_mf = (const int*)d_in[6];
    }
    const float* Wk0   = (const float*)d_in[7];
    const float* bk0   = (const float*)d_in[8];
    const float* Wk1   = (const float*)d_in[9];
    const float* bk1   = (const float*)d_in[10];
    const float* Wk2   = (const float*)d_in[11];
    const float* bk2   = (const float*)d_in[12];
    const float* Wroot = (const float*)d_in[13];
    const float* broot = (const float*)d_in[14];
    const float* Wq    = (const float*)d_in[15];
    const float* Wkk   = (const float*)d_in[16];
    const float* Wv    = (const float*)d_in[17];
    const float* We    = (const float*)d_in[18];
    const float* Wo    = (const float*)d_in[19];
    const float* bo    = (const float*)d_in[20];
    const float* Wt1   = (const float*)d_in[21];
    const float* bt1   = (const float*)d_in[22];
    const float* Wt2   = (const float*)d_in[23];
    const float* bt2   = (const float*)d_in[24];
    float* out = (float*)d_out;

    unsigned *p_mkey; float *p_z, *p_xc, *p_aggr; int* p_cnt;
    cudaGetSymbolAddress((void**)&p_mkey, g_mkey);
    cudaGetSymbolAddress((void**)&p_z,    g_z);
    cudaGetSymbolAddress((void**)&p_xc,   g_xc);
    cudaGetSymbolAddress((void**)&p_aggr, g_aggr);
    cudaGetSymbolAddress((void**)&p_cnt,  g_cnt);
    float *p_q, *p_kk, *p_v, *p_c;
    cudaGetSymbolAddress((void**)&p_q,   g_q);
    cudaGetSymbolAddress((void**)&p_kk,  g_kk);
    cudaGetSymbolAddress((void**)&p_v,   g_v);
    cudaGetSymbolAddress((void**)&p_c,   g_c);

    // -- weight conversion first; gemm_h early so profiler window lands on it --
    conv_w2t<<<(DIMV * W2N + 255) / 256, 256>>>(Wk2);                 // 0
    conv_wk1<<<(KWN * KWN + 255) / 256, 256>>>(Wk1);                  // 1
    conv_x<<<((NF + 512) * DIMV + 255) / 256, 256>>>(x_flow);         // 2
    gemm_h_mma<<<dim3(4, (EFFN + 127) / 128), 256>>>(ea_ff, Wk0, bk0, bk1); // 3
    gemm_m_mma<<<dim3(W2N / 128, 4), 256>>>(0);                       // 4

    // init zeros
    zero_u32<<<640, 256>>>((unsigned*)p_aggr, NF * 64);
    zero_u32<<<160, 256>>>(p_mkey, NF);
    zero_u32<<<160, 256>>>((unsigned*)p_z, NF);
    zero_u32<<<640, 256>>>((unsigned*)p_xc, NF * 64);
    zero_u32<<<160, 256>>>((unsigned*)p_cnt, NF);

    // small GEMMs: q, k, v, c
    {
        dim3 g1(1, (NF + 127) / 128);
        sgemm<false><<<g1, 256>>>(x_flow, Wq, nullptr, p_q, NF, 64, 64);
        dim3 g2(1, (NMB + 127) / 128);
        sgemm<false><<<g2, 256>>>(x_memb, Wkk, nullptr, p_kk, NMB, 64, 64);
        sgemm<false><<<g2, 256>>>(x_memb, Wv, nullptr, p_v, NMB, 64, 64);
        sgemm<false><<<g1, 256>>>(x_flow, bk2, nullptr, p_c, NF, 64, 64);
    }

    // attention path
    score_kernel<<<(EMFN + 7) / 8, 256>>>(ei_mf, ea_mf, We);
    exp_kernel<<<(EMFN + 255) / 256, 256>>>(ei_mf);
    xcacc_kernel<<<(EMFN + 7) / 8, 256>>>(ei_mf);
    dual64_kernel<<<(NF + 3) / 4, 256>>>(x_flow, Wroot, broot, Wo, bo);

    // CSR by src
    cnt_kernel<<<(EFFN + 255) / 256, 256>>>(ei_ff);
    scan_kernel<<<1, 1024>>>();
    fill_kernel<<<(EFFN + 255) / 256, 256>>>(ei_ff);

    // slab 0 msg (gemm_m slab0 already launched above), then remaining slabs
    msg_kernel<<<SLAB, 256>>>(ei_ff, 0);
    for (int s = 1; s < NSLAB; s++) {
        gemm_m_mma<<<dim3(W2N / 128, 4), 256>>>(s);
        msg_kernel<<<SLAB, 256>>>(ei_ff, s);
    }

    // FiLM epilogue
    ss_kernel<<<1, 128>>>(tau, Wt1, bt1, Wt2, bt2);
    final_kernel<<<(NF * 64 + 255) / 256, 256>>>(out);
}

// round 16
// speedup vs baseline: 1.2288x; 1.0215x over previous
#include <cuda_runtime.h>
#include <cuda_bf16.h>
#include <cuda_fp16.h>
#include <math.h>
#include <stdint.h>

#define NF    20000
#define NMB   5000
#define EFFN  100000
#define EMFN  80000
#define DIMV  64
#define KWN   512
#define SLAB  500
#define NSLAB 40
#define W2N   32768            // KWN * DIMV

#define A_LD  24               // 16 k + 8 pad (ushort)
#define B_LD  136              // 128 n + 8 pad (ushort)

typedef unsigned long long u64t;

// ---------------- device scratch (__device__ globals; no allocations) ----------------
__device__ unsigned short g_h [(size_t)EFFN * KWN];     // 102.4 MB fp16
__device__ unsigned short g_M [(size_t)SLAB * W2N];     // 32.8 MB fp16
__device__ unsigned short g_W2T_h[(size_t)DIMV * W2N];  // 4 MB  fp16 [d][n=k*64+f]
__device__ unsigned short g_Wk1_h[KWN * KWN];           // 512 KB fp16 [k][n]
__device__ unsigned short g_x_hi[(NF + 512) * DIMV];    // fp16 hi
__device__ unsigned short g_x_lo[(NF + 512) * DIMV];    // fp16 lo
__device__ float    g_q [NF * DIMV];
__device__ float    g_kk[NMB * DIMV];
__device__ float    g_v [NMB * DIMV];
__device__ float    g_c [NF * DIMV];
__device__ float    g_score[EMFN];
__device__ float    g_av[EMFN];
__device__ unsigned g_mkey[NF];
__device__ float    g_z[NF];
__device__ float    g_xc[NF * DIMV];
__device__ float    g_base[NF * DIMV];
__device__ float    g_aggr[NF * DIMV];
__device__ int      g_cnt[NF];
__device__ int      g_off[NF + 1];
__device__ int      g_pos[NF];
__device__ int      g_perm[EFFN];
__device__ float    g_ss[2 * DIMV];

// ---------------- helpers ----------------
__device__ __forceinline__ unsigned kenc(float f) {
    unsigned b = __float_as_uint(f);
    return (b & 0x80000000u) ? ~b : (b | 0x80000000u);
}
__device__ __forceinline__ float kdec(unsigned u) {
    return (u & 0x80000000u) ? __uint_as_float(u ^ 0x80000000u) : __uint_as_float(~u);
}
__device__ __forceinline__ float silu(float y) { return y / (1.f + expf(-y)); }

__device__ __forceinline__ u64t pack_dup(float x) {
    u64t r; asm("mov.b64 %0, {%1, %1};" : "=l"(r) : "r"(__float_as_uint(x))); return r;
}
__device__ __forceinline__ u64t pack2(float lo, float hi) {
    u64t r; asm("mov.b64 %0, {%1, %2};" : "=l"(r) : "r"(__float_as_uint(lo)), "r"(__float_as_uint(hi))); return r;
}
__device__ __forceinline__ void fma2(u64t& d, u64t a, u64t b) {
    asm("fma.rn.f32x2 %0, %1, %2, %0;" : "+l"(d) : "l"(a), "l"(b));
}

__device__ __forceinline__ uint32_t smem_u32(const void* p) {
    uint32_t a;
    asm("{ .reg .u64 t; cvta.to.shared.u64 t, %1; cvt.u32.u64 %0, t; }" : "=r"(a) : "l"(p));
    return a;
}
__device__ __forceinline__ void ldsm4(uint32_t& r0, uint32_t& r1, uint32_t& r2, uint32_t& r3, uint32_t a) {
    asm volatile("ldmatrix.sync.aligned.m8n8.x4.shared.b16 {%0,%1,%2,%3}, [%4];"
        : "=r"(r0), "=r"(r1), "=r"(r2), "=r"(r3) : "r"(a));
}
__device__ __forceinline__ void ldsm4t(uint32_t& r0, uint32_t& r1, uint32_t& r2, uint32_t& r3, uint32_t a) {
    asm volatile("ldmatrix.sync.aligned.m8n8.x4.trans.shared.b16 {%0,%1,%2,%3}, [%4];"
        : "=r"(r0), "=r"(r1), "=r"(r2), "=r"(r3) : "r"(a));
}
__device__ __forceinline__ void mma_f16(float* c, const uint32_t* a, uint32_t b0, uint32_t b1) {
    asm volatile(
        "mma.sync.aligned.m16n8k16.row.col.f32.f16.f16.f32 "
        "{%0,%1,%2,%3}, {%4,%5,%6,%7}, {%8,%9}, {%0,%1,%2,%3};"
        : "+f"(c[0]), "+f"(c[1]), "+f"(c[2]), "+f"(c[3])
        : "r"(a[0]), "r"(a[1]), "r"(a[2]), "r"(a[3]), "r"(b0), "r"(b1));
}

// fp16 hi/lo split of 8 consecutive floats -> two 16B packets (A side, exact to ~2^-22)
__device__ __forceinline__ void split8h(const float* s, uint4& hi, uint4& lo) {
    unsigned short h[8], l[8];
#pragma unroll
    for (int i = 0; i < 8; i++) {
        float f = s[i];
        __half bh = __float2half_rn(f);
        __half bl = __float2half_rn(f - __half2float(bh));
        h[i] = __half_as_ushort(bh);
        l[i] = __half_as_ushort(bl);
    }
    hi.x = h[0] | ((unsigned)h[1] << 16); hi.y = h[2] | ((unsigned)h[3] << 16);
    hi.z = h[4] | ((unsigned)h[5] << 16); hi.w = h[6] | ((unsigned)h[7] << 16);
    lo.x = l[0] | ((unsigned)l[1] << 16); lo.y = l[2] | ((unsigned)l[3] << 16);
    lo.z = l[4] | ((unsigned)l[5] << 16); lo.w = l[6] | ((unsigned)l[7] << 16);
}

// warp-tile kstep (fp16x2): c[2][8][4] += (Ahi+Alo)[32x16] * B[16x64]
__device__ __forceinline__ void warp_kstep(float c[2][8][4],
        const unsigned short* Ahi, const unsigned short* Alo,
        const unsigned short* Bs,
        int warp_m, int warp_n, int lane) {
    int arow = lane & 15;
    int acol = (lane >> 4) << 3;
    uint32_t ahi[2][4], alo[2][4];
#pragma unroll
    for (int mi = 0; mi < 2; mi++) {
        int r = warp_m * 32 + mi * 16 + arow;
        ldsm4(ahi[mi][0], ahi[mi][1], ahi[mi][2], ahi[mi][3], smem_u32(Ahi + r * A_LD + acol));
        ldsm4(alo[mi][0], alo[mi][1], alo[mi][2], alo[mi][3], smem_u32(Alo + r * A_LD + acol));
    }
#pragma unroll
    for (int nh = 0; nh < 2; nh++) {
        uint32_t b[2][4];
#pragma unroll
        for (int ni = 0; ni < 2; ni++) {
            int ncol = warp_n * 64 + nh * 32 + ni * 16 + acol;
            ldsm4t(b[ni][0], b[ni][1], b[ni][2], b[ni][3], smem_u32(Bs + arow * B_LD + ncol));
        }
#pragma unroll
        for (int mi = 0; mi < 2; mi++)
#pragma unroll
            for (int ni = 0; ni < 2; ni++) {
                int n8 = nh * 4 + ni * 2;
                mma_f16(c[mi][n8],     ahi[mi], b[ni][0], b[ni][1]);
                mma_f16(c[mi][n8 + 1], ahi[mi], b[ni][2], b[ni][3]);
                mma_f16(c[mi][n8],     alo[mi], b[ni][0], b[ni][1]);
                mma_f16(c[mi][n8 + 1], alo[mi], b[ni][2], b[ni][3]);
            }
    }
}

// ---------------- tiny utility kernels ----------------
__global__ void zero_u32(unsigned* p, int n) {
    for (int i = blockIdx.x * blockDim.x + threadIdx.x; i < n; i += gridDim.x * blockDim.x)
        p[i] = 0u;
}

// Wk1 [k][n] -> fp16
__global__ void conv_wk1(const float* __restrict__ Wk1) {
    int idx = blockIdx.x * blockDim.x + threadIdx.x;
    if (idx >= KWN * KWN) return;
    g_Wk1_h[idx] = __half_as_ushort(__float2half_rn(Wk1[idx]));
}

// W2T[d][n=k*64+f] = Wk2[k*4096 + d*64 + f] -> fp16
__global__ void conv_w2t(const float* __restrict__ Wk2) {
    int idx = blockIdx.x * blockDim.x + threadIdx.x;
    if (idx >= DIMV * W2N) return;
    int d = idx >> 15;
    int r = idx & 32767;
    int k = r >> 6;
    int f = r & 63;
    g_W2T_h[idx] = __half_as_ushort(__float2half_rn(Wk2[k * 4096 + d * 64 + f]));
}

// x_flow -> fp16 hi/lo (A side of gemm_m, exact)
__global__ void conv_x(const float* __restrict__ x_flow) {
    int idx = blockIdx.x * blockDim.x + threadIdx.x;
    if (idx >= (NF + 512) * DIMV) return;
    float v = (idx < NF * DIMV) ? x_flow[idx] : 0.f;
    __half bh = __float2half_rn(v);
    __half bl = __float2half_rn(v - __half2float(bh));
    g_x_hi[idx] = __half_as_ushort(bh);
    g_x_lo[idx] = __half_as_ushort(bl);
}

// ---------------- HMMA GEMM 1 (fused h0): h = relu(relu(ea@Wk0+bk0) @ Wk1 + bk1) -> fp16 ----------------
__global__ void __launch_bounds__(256, 2)
gemm_h_mma(const float* __restrict__ ea_ff, const float* __restrict__ Wk0,
           const float* __restrict__ bk0, const float* __restrict__ bk1) {
    __shared__ __align__(16) unsigned short Ahi[128 * A_LD], Alo[128 * A_LD];
    __shared__ __align__(16) unsigned short Bs[16 * B_LD];
    __shared__ float sWk0[6 * KWN];   // 12 KB
    __shared__ float sbk0[KWN];       // 2 KB
    int tid = threadIdx.x, wid = tid >> 5, lane = tid & 31;
    int warp_m = wid & 3, warp_n = wid >> 2;
    int tm = blockIdx.y, tn = blockIdx.x;

    for (int i = tid; i < 6 * KWN; i += 256) sWk0[i] = Wk0[i];
    for (int i = tid; i < KWN; i += 256) sbk0[i] = bk0[i];

    int arow_g = tm * 128 + (tid >> 1);
    float a6[6];
    {
        bool valid = arow_g < EFFN;
        const float* ea = ea_ff + (size_t)(valid ? arow_g : 0) * 6;
#pragma unroll
        for (int j = 0; j < 6; j++) a6[j] = valid ? ea[j] : 0.f;
    }
    __syncthreads();

    int ar = tid >> 1, ac = (tid & 1) * 8;
    int bkr = tid >> 4, bc = (tid & 15) * 8;

    float c[2][8][4];
#pragma unroll
    for (int i = 0; i < 2; i++)
#pragma unroll
        for (int j = 0; j < 8; j++)
#pragma unroll
            for (int q = 0; q < 4; q++) c[i][j][q] = 0.f;

    for (int kc = 0; kc < 32; kc++) {
        {
            float v[8];
#pragma unroll
            for (int i = 0; i < 8; i++) {
                int k = kc * 16 + ac + i;
                float s = sbk0[k];
#pragma unroll
                for (int j = 0; j < 6; j++) s = fmaf(a6[j], sWk0[j * KWN + k], s);
                v[i] = fmaxf(s, 0.f);
            }
            uint4 hi, lo;
            split8h(v, hi, lo);
            *(uint4*)&Ahi[ar * A_LD + ac] = hi;
            *(uint4*)&Alo[ar * A_LD + ac] = lo;
        }
        {
            size_t src = (size_t)(kc * 16 + bkr) * KWN + tn * 128 + bc;
            *(uint4*)&Bs[bkr * B_LD + bc] = *(const uint4*)&g_Wk1_h[src];
        }
        __syncthreads();
        warp_kstep(c, Ahi, Alo, Bs, warp_m, warp_n, lane);
        __syncthreads();
    }

    // epilogue: bias + relu, pack half2, store 4B per 2 cols
    int rbase = tm * 128 + warp_m * 32 + (lane >> 2);
    int cbase = tn * 128 + warp_n * 64 + (lane & 3) * 2;
#pragma unroll
    for (int mi = 0; mi < 2; mi++) {
#pragma unroll
        for (int n8 = 0; n8 < 8; n8++) {
            int col = cbase + n8 * 8;
            float b0 = bk1[col], b1 = bk1[col + 1];
            int r0 = rbase + mi * 16;
            if (r0 < EFFN) {
                __half2 hv = __floats2half2_rn(fmaxf(c[mi][n8][0] + b0, 0.f),
                                               fmaxf(c[mi][n8][1] + b1, 0.f));
                *(uint32_t*)&g_h[(size_t)r0 * KWN + col] = *(uint32_t*)&hv;
            }
            int r1 = r0 + 8;
            if (r1 < EFFN) {
                __half2 hv = __floats2half2_rn(fmaxf(c[mi][n8][2] + b0, 0.f),
                                               fmaxf(c[mi][n8][3] + b1, 0.f));
                *(uint32_t*)&g_h[(size_t)r1 * KWN + col] = *(uint32_t*)&hv;
            }
        }
    }
}

// ---------------- HMMA GEMM 2: M_slab = x_slab @ W2T  [500 x 32768], K=64 -> fp16 ----------------
__global__ void __launch_bounds__(256, 2)
gemm_m_mma(int slab) {
    __shared__ __align__(16) unsigned short Ahi[128 * A_LD], Alo[128 * A_LD];
    __shared__ __align__(16) unsigned short Bs[16 * B_LD];
    int tid = threadIdx.x, wid = tid >> 5, lane = tid & 31;
    int warp_m = wid & 3, warp_n = wid >> 2;
    int tm = blockIdx.y, tn = blockIdx.x;

    float c[2][8][4];
#pragma unroll
    for (int i = 0; i < 2; i++)
#pragma unroll
        for (int j = 0; j < 8; j++)
#pragma unroll
            for (int q = 0; q < 4; q++) c[i][j][q] = 0.f;

    int ar = tid >> 1, ac = (tid & 1) * 8;
    int bkr = tid >> 4, bc = (tid & 15) * 8;

    for (int kc = 0; kc < DIMV / 16; kc++) {
        {
            size_t src = (size_t)(slab * SLAB + tm * 128 + ar) * DIMV + kc * 16 + ac;
            *(uint4*)&Ahi[ar * A_LD + ac] = *(const uint4*)&g_x_hi[src];
            *(uint4*)&Alo[ar * A_LD + ac] = *(const uint4*)&g_x_lo[src];
        }
        {
            size_t src = (size_t)(kc * 16 + bkr) * W2N + tn * 128 + bc;
            *(uint4*)&Bs[bkr * B_LD + bc] = *(const uint4*)&g_W2T_h[src];
        }
        __syncthreads();
        warp_kstep(c, Ahi, Alo, Bs, warp_m, warp_n, lane);
        __syncthreads();
    }

    int rbase = tm * 128 + warp_m * 32 + (lane >> 2);
    int cbase = tn * 128 + warp_n * 64 + (lane & 3) * 2;
#pragma unroll
    for (int mi = 0; mi < 2; mi++) {
#pragma unroll
        for (int n8 = 0; n8 < 8; n8++) {
            int col = cbase + n8 * 8;
            int r0 = rbase + mi * 16;
            if (r0 < SLAB) {
                __half2 hv = __floats2half2_rn(c[mi][n8][0], c[mi][n8][1]);
                *(uint32_t*)&g_M[(size_t)r0 * W2N + col] = *(uint32_t*)&hv;
            }
            int r1 = r0 + 8;
            if (r1 < SLAB) {
                __half2 hv = __floats2half2_rn(c[mi][n8][2], c[mi][n8][3]);
                *(uint32_t*)&g_M[(size_t)r1 * W2N + col] = *(uint32_t*)&hv;
            }
        }
    }
}

// ---------------- generic tiled SGEMM (FFMA2): small GEMMs ----------------
template <bool RELU>
__global__ void __launch_bounds__(256, 2)
sgemm(const float* __restrict__ A, const float* __restrict__ B,
      const float* __restrict__ bias, float* __restrict__ C,
      int M, int N, int K) {
    __shared__ __align__(16) float As[16][132];
    __shared__ __align__(16) float Bs[16][128];
    int bm = blockIdx.y * 128, bn = blockIdx.x * 128;
    int tid = threadIdx.x;
    int tr = tid >> 4, tc = tid & 15;
    bool k4 = ((K & 3) == 0);

    u64t acc2[8][4];
#pragma unroll
    for (int i = 0; i < 8; i++)
#pragma unroll
        for (int j = 0; j < 4; j++) acc2[i][j] = 0ull;

    for (int kt = 0; kt < K; kt += 16) {
#pragma unroll
        for (int l = 0; l < 2; l++) {
            int lin = tid + l * 256;
            int row = lin >> 2;
            int kq  = (lin & 3) * 4;
            float4 v = make_float4(0.f, 0.f, 0.f, 0.f);
            int gr = bm + row;
            if (gr < M) {
                int k0 = kt + kq;
                if (k4 && k0 + 3 < K) {
                    v = *(const float4*)&A[(size_t)gr * K + k0];
                } else {
                    float t0[4] = {0.f, 0.f, 0.f, 0.f};
#pragma unroll
                    for (int i = 0; i < 4; i++)
                        if (k0 + i < K) t0[i] = A[(size_t)gr * K + k0 + i];
                    v = make_float4(t0[0], t0[1], t0[2], t0[3]);
                }
            }
            As[kq + 0][row] = v.x; As[kq + 1][row] = v.y;
            As[kq + 2][row] = v.z; As[kq + 3][row] = v.w;
        }
#pragma unroll
        for (int l = 0; l < 2; l++) {
            int lin = tid + l * 256;
            int kr = lin >> 5;
            int nq = (lin & 31) * 4;
            float4 v = make_float4(0.f, 0.f, 0.f, 0.f);
            int gk = kt + kr, gn = bn + nq;
            if (gk < K && gn + 3 < N)
                v = *(const float4*)&B[(size_t)gk * N + gn];
            *(float4*)&Bs[kr][nq] = v;
        }
        __syncthreads();
#pragma unroll
        for (int k = 0; k < 16; k++) {
            float a[8];
            *(float4*)&a[0] = *(const float4*)&As[k][tr * 8];
            *(float4*)&a[4] = *(const float4*)&As[k][tr * 8 + 4];
            u64t b2[4];
            const u64t* bp = (const u64t*)&Bs[k][tc * 8];
            b2[0] = bp[0]; b2[1] = bp[1]; b2[2] = bp[2]; b2[3] = bp[3];
#pragma unroll
            for (int i = 0; i < 8; i++) {
                u64t ad = pack_dup(a[i]);
#pragma unroll
                for (int j = 0; j < 4; j++) fma2(acc2[i][j], ad, b2[j]);
            }
        }
        __syncthreads();
    }
#pragma unroll
    for (int i = 0; i < 8; i++) {
        int gr = bm + tr * 8 + i;
        if (gr >= M) continue;
#pragma unroll
        for (int j = 0; j < 4; j++) {
            float2 p = *(float2*)&acc2[i][j];
            int gn0 = bn + tc * 8 + 2 * j;
#pragma unroll
            for (int s = 0; s < 2; s++) {
                int gn = gn0 + s;
                if (gn >= N) continue;
                float v = (s == 0) ? p.x : p.y;
                if (bias) v += bias[gn];
                if (RELU) v = fmaxf(v, 0.f);
                C[(size_t)gr * N + gn] = v;
            }
        }
    }
}

// ---------------- attention path ----------------
__global__ void score_kernel(const int* __restrict__ ei_mf, const float* __restrict__ ea_mf,
                             const float* __restrict__ We) {
    __shared__ float sWe[6 * 64];
    int tid = threadIdx.x;
    for (int i = tid; i < 6 * 64; i += blockDim.x) sWe[i] = We[i];
    __syncthreads();
    int e = blockIdx.x * 8 + (tid >> 5);
    if (e >= EMFN) return;
    int l = tid & 31;
    int src = ei_mf[e];
    int dst = ei_mf[EMFN + e];
    float ke0 = g_kk[src * 64 + l];
    float ke1 = g_kk[src * 64 + 32 + l];
#pragma unroll
    for (int j = 0; j < 6; j++) {
        float ea = ea_mf[e * 6 + j];
        ke0 = fmaf(ea, sWe[j * 64 + l], ke0);
        ke1 = fmaf(ea, sWe[j * 64 + 32 + l], ke1);
    }
    float s = g_q[dst * 64 + l] * ke0 + g_q[dst * 64 + 32 + l] * ke1;
#pragma unroll
    for (int off = 16; off; off >>= 1) s += __shfl_down_sync(0xffffffffu, s, off);
    if (l == 0) {
        s *= 0.125f;
        g_score[e] = s;
        atomicMax(&g_mkey[dst], kenc(s));
    }
}

__global__ void exp_kernel(const int* __restrict__ ei_mf) {
    int e = blockIdx.x * blockDim.x + threadIdx.x;
    if (e >= EMFN) return;
    int dst = ei_mf[EMFN + e];
    float a = expf(g_score[e] - kdec(g_mkey[dst]));
    g_av[e] = a;
    atomicAdd(&g_z[dst], a);
}

__global__ void xcacc_kernel(const int* __restrict__ ei_mf) {
    int e = blockIdx.x * 8 + (threadIdx.x >> 5);
    if (e >= EMFN) return;
    int l = threadIdx.x & 31;
    int src = ei_mf[e];
    int dst = ei_mf[EMFN + e];
    float alpha = g_av[e] / (g_z[dst] + 1e-9f);
    atomicAdd(&g_xc[dst * 64 + l],      alpha * g_v[src * 64 + l]);
    atomicAdd(&g_xc[dst * 64 + 32 + l], alpha * g_v[src * 64 + 32 + l]);
}

__global__ void dual64_kernel(const float* __restrict__ x, const float* __restrict__ Wroot,
                              const float* __restrict__ broot, const float* __restrict__ Wo,
                              const float* __restrict__ bo) {
    __shared__ float sWr[64 * 64], sWo[64 * 64], sx[4][64], sxc[4][64];
    int tid = threadIdx.x;
    for (int i = tid; i < 4096; i += 256) { sWr[i] = Wroot[i]; sWo[i] = Wo[i]; }
    int r0 = blockIdx.x * 4;
    {
        int rr = tid >> 6, cc = tid & 63;
        int gr = r0 + rr;
        sx[rr][cc]  = (gr < NF) ? x[gr * 64 + cc]    : 0.f;
        sxc[rr][cc] = (gr < NF) ? g_xc[gr * 64 + cc] : 0.f;
    }
    __syncthreads();
    int rr = tid >> 6, cc = tid & 63;
    int gr = r0 + rr;
    if (gr < NF) {
        float s = broot[cc] + bo[cc];
#pragma unroll 8
        for (int d = 0; d < 64; d++)
            s += sx[rr][d] * sWr[d * 64 + cc] + sxc[rr][d] * sWo[d * 64 + cc];
        g_base[gr * 64 + cc] = s;
    }
}

// ---------------- CSR by src over ff-edges ----------------
__global__ void cnt_kernel(const int* __restrict__ ei_ff) {
    int e = blockIdx.x * blockDim.x + threadIdx.x;
    if (e < EFFN) atomicAdd(&g_cnt[ei_ff[e]], 1);
}

__global__ void scan_kernel() {
    __shared__ int s[1024];
    __shared__ int carry;
    int tid = threadIdx.x;
    if (tid == 0) carry = 0;
    __syncthreads();
    for (int base = 0; base < NF; base += 1024) {
        int i = base + tid;
        int v = (i < NF) ? g_cnt[i] : 0;
        s[tid] = v;
        __syncthreads();
        for (int off = 1; off < 1024; off <<= 1) {
            int t = (tid >= off) ? s[tid - off] : 0;
            __syncthreads();
            s[tid] += t;
            __syncthreads();
        }
        if (i < NF) { int ex = carry + s[tid] - v; g_off[i] = ex; g_pos[i] = ex; }
        __syncthreads();
        if (tid == 0) carry += s[1023];
        __syncthreads();
    }
    if (tid == 0) g_off[NF] = carry;
}

__global__ void fill_kernel(const int* __restrict__ ei_ff) {
    int e = blockIdx.x * blockDim.x + threadIdx.x;
    if (e < EFFN) {
        int p = atomicAdd(&g_pos[ei_ff[e]], 1);
        g_perm[p] = e;
    }
}

// ---------------- phase B: per-node msg = h[e] @ M[node] -> atomic aggr[dst] ----------------
__global__ void __launch_bounds__(256)
msg_kernel(const int* __restrict__ ei_ff, int slab) {
    __shared__ __align__(16) float Ms[128][64];
    __shared__ __align__(16) float hs[8][128];
    __shared__ float red[8][4][64];
    int tid = threadIdx.x;
    int nl = blockIdx.x;
    int n  = slab * SLAB + nl;
    int begin = g_off[n], end = g_off[n + 1];
    if (begin == end) return;
    int f = tid & 63, slice = tid >> 6;
    const unsigned short* Mrow = g_M + (size_t)nl * W2N;
    float cbias = g_c[n * 64 + f];

    for (int e0 = begin; e0 < end; e0 += 8) {
        int ec = min(8, end - e0);
        u64t acc2[8];
#pragma unroll
        for (int j = 0; j < 8; j++) acc2[j] = 0ull;

        for (int kt = 0; kt < 4; kt++) {
            // load M tile (128k x 64f) fp16 -> fp32 smem
#pragma unroll
            for (int l = 0; l < 4; l++) {
                int lin = tid + l * 256;            // 0..1023, 8 halves each
                int k  = lin >> 3;
                int fq = (lin & 7) * 8;
                uint4 pk = *(const uint4*)&Mrow[(size_t)(kt * 128 + k) * 64 + fq];
                const __half2* hp = (const __half2*)&pk;
                float2 f0 = __half22float2(hp[0]);
                float2 f1 = __half22float2(hp[1]);
                float2 f2 = __half22float2(hp[2]);
                float2 f3 = __half22float2(hp[3]);
                *(float4*)&Ms[k][fq]     = make_float4(f0.x, f0.y, f1.x, f1.y);
                *(float4*)&Ms[k][fq + 4] = make_float4(f2.x, f2.y, f3.x, f3.y);
            }
            // load h tile (8 edges x 128 k) fp16 -> fp32 smem, threads 0..127
            if (tid < 128) {
                int j  = tid >> 4;
                int kq = (tid & 15) * 8;
                uint4 pk = make_uint4(0, 0, 0, 0);
                if (j < ec) {
                    int e = g_perm[e0 + j];
                    pk = *(const uint4*)&g_h[(size_t)e * KWN + kt * 128 + kq];
                }
                const __half2* hp = (const __half2*)&pk;
                float2 f0 = __half22float2(hp[0]);
                float2 f1 = __half22float2(hp[1]);
                float2 f2 = __half22float2(hp[2]);
                float2 f3 = __half22float2(hp[3]);
                *(float4*)&hs[j][kq]     = make_float4(f0.x, f0.y, f1.x, f1.y);
                *(float4*)&hs[j][kq + 4] = make_float4(f2.x, f2.y, f3.x, f3.y);
            }
            __syncthreads();
#pragma unroll
            for (int kk2 = 0; kk2 < 16; kk2++) {
                int k = slice * 32 + kk2 * 2;
                u64t m2 = pack2(Ms[k][f], Ms[k + 1][f]);
#pragma unroll
                for (int j = 0; j < 8; j++) {
                    u64t h2 = *(const u64t*)&hs[j][k];
                    fma2(acc2[j], h2, m2);
                }
            }
            __syncthreads();
        }
        for (int j = 0; j < ec; j++) {
            float2 p = *(float2*)&acc2[j];
            red[j][slice][f] = p.x + p.y;
        }
        __syncthreads();
        for (int jb = 0; jb < ec; jb += 4) {
            int j = jb + (tid >> 6);
            if (j < ec) {
                float s = red[j][0][f] + red[j][1][f] + red[j][2][f] + red[j][3][f] + cbias;
                int e = g_perm[e0 + j];
                int dst = ei_ff[EFFN + e];
                atomicAdd(&g_aggr[dst * 64 + f], s);
            }
        }
        __syncthreads();
    }
}

// ---------------- FiLM epilogue ----------------
__global__ void ss_kernel(const float* __restrict__ tau, const float* __restrict__ Wt1,
                          const float* __restrict__ bt1, const float* __restrict__ Wt2,
                          const float* __restrict__ bt2) {
    __shared__ float temb[64];
    int tid = threadIdx.x;
    if (tid < 64) temb[tid] = silu(tau[0] * Wt1[tid] + bt1[tid]);
    __syncthreads();
    if (tid < 128) {
        float s = bt2[tid];
        for (int d = 0; d < 64; d++) s += temb[d] * Wt2[d * 128 + tid];
        g_ss[tid] = s;
    }
}

__global__ void final_kernel(float* __restrict__ out) {
    int idx = blockIdx.x * blockDim.x + threadIdx.x;
    if (idx >= NF * 64) return;
    int fcol = idx & 63;
    float g = g_base[idx] + g_aggr[idx];
    g = fmaxf(g, 0.f);
    float y = g * (1.f + g_ss[fcol]) + g_ss[64 + fcol];
    out[idx] = silu(y);
}

// ---------------- host ----------------
extern "C" void kernel_launch(void* const* d_in, const int* in_sizes, int n_in,
                              void* d_out, int out_size) {
    const float* x_flow = (const float*)d_in[0];
    const float* x_memb = (const float*)d_in[1];
    const int *ei_ff, *ei_mf;
    const float *ea_ff, *ea_mf, *tau;
    if (in_sizes[2] == 2 * EFFN) {
        ei_ff = (const int*)d_in[2];  ea_ff = (const float*)d_in[3];
        ei_mf = (const int*)d_in[4];  ea_mf = (const float*)d_in[5];
        tau   = (const float*)d_in[6];
    } else {
        ea_ff = (const float*)d_in[2]; ea_mf = (const float*)d_in[3];
        tau   = (const float*)d_in[4];
        ei_ff = (const int*)d_in[5];   ei_mf = (const int*)d_in[6];
    }
    const float* Wk0   = (const float*)d_in[7];
    const float* bk0   = (const float*)d_in[8];
    const float* Wk1   = (const float*)d_in[9];
    const float* bk1   = (const float*)d_in[10];
    const float* Wk2   = (const float*)d_in[11];
    const float* bk2   = (const float*)d_in[12];
    const float* Wroot = (const float*)d_in[13];
    const float* broot = (const float*)d_in[14];
    const float* Wq    = (const float*)d_in[15];
    const float* Wkk   = (const float*)d_in[16];
    const float* Wv    = (const float*)d_in[17];
    const float* We    = (const float*)d_in[18];
    const float* Wo    = (const float*)d_in[19];
    const float* bo    = (const float*)d_in[20];
    const float* Wt1   = (const float*)d_in[21];
    const float* bt1   = (const float*)d_in[22];
    const float* Wt2   = (const float*)d_in[23];
    const float* bt2   = (const float*)d_in[24];
    float* out = (float*)d_out;

    unsigned *p_mkey; float *p_z, *p_xc, *p_aggr; int* p_cnt;
    cudaGetSymbolAddress((void**)&p_mkey, g_mkey);
    cudaGetSymbolAddress((void**)&p_z,    g_z);
    cudaGetSymbolAddress((void**)&p_xc,   g_xc);
    cudaGetSymbolAddress((void**)&p_aggr, g_aggr);
    cudaGetSymbolAddress((void**)&p_cnt,  g_cnt);
    float *p_q, *p_kk, *p_v, *p_c;
    cudaGetSymbolAddress((void**)&p_q,   g_q);
    cudaGetSymbolAddress((void**)&p_kk,  g_kk);
    cudaGetSymbolAddress((void**)&p_v,   g_v);
    cudaGetSymbolAddress((void**)&p_c,   g_c);

    // -- weight conversion first; gemm_h early so profiler window lands on it --
    conv_w2t<<<(DIMV * W2N + 255) / 256, 256>>>(Wk2);                 // 0
    conv_wk1<<<(KWN * KWN + 255) / 256, 256>>>(Wk1);                  // 1
    conv_x<<<((NF + 512) * DIMV + 255) / 256, 256>>>(x_flow);         // 2
    gemm_h_mma<<<dim3(4, (EFFN + 127) / 128), 256>>>(ea_ff, Wk0, bk0, bk1); // 3
    gemm_m_mma<<<dim3(W2N / 128, 4), 256>>>(0);                       // 4

    // init zeros
    zero_u32<<<640, 256>>>((unsigned*)p_aggr, NF * 64);
    zero_u32<<<160, 256>>>(p_mkey, NF);
    zero_u32<<<160, 256>>>((unsigned*)p_z, NF);
    zero_u32<<<640, 256>>>((unsigned*)p_xc, NF * 64);
    zero_u32<<<160, 256>>>((unsigned*)p_cnt, NF);

    // small GEMMs: q, k, v, c
    {
        dim3 g1(1, (NF + 127) / 128);
        sgemm<false><<<g1, 256>>>(x_flow, Wq, nullptr, p_q, NF, 64, 64);
        dim3 g2(1, (NMB + 127) / 128);
        sgemm<false><<<g2, 256>>>(x_memb, Wkk, nullptr, p_kk, NMB, 64, 64);
        sgemm<false><<<g2, 256>>>(x_memb, Wv, nullptr, p_v, NMB, 64, 64);
        sgemm<false><<<g1, 256>>>(x_flow, bk2, nullptr, p_c, NF, 64, 64);
    }

    // attention path
    score_kernel<<<(EMFN + 7) / 8, 256>>>(ei_mf, ea_mf, We);
    exp_kernel<<<(EMFN + 255) / 256, 256>>>(ei_mf);
    xcacc_kernel<<<(EMFN + 7) / 8, 256>>>(ei_mf);
    dual64_kernel<<<(NF + 3) / 4, 256>>>(x_flow, Wroot, broot, Wo, bo);

    // CSR by src
    cnt_kernel<<<(EFFN + 255) / 256, 256>>>(ei_ff);
    scan_kernel<<<1, 1024>>>();
    fill_kernel<<<(EFFN + 255) / 256, 256>>>(ei_ff);

    // slab 0 msg (gemm_m slab0 already launched above), then remaining slabs
    msg_kernel<<<SLAB, 256>>>(ei_ff, 0);
    for (int s = 1; s < NSLAB; s++) {
        gemm_m_mma<<<dim3(W2N / 128, 4), 256>>>(s);
        msg_kernel<<<SLAB, 256>>>(ei_ff, s);
    }

    // FiLM epilogue
    ss_kernel<<<1, 128>>>(tau, Wt1, bt1, Wt2, bt2);
    final_kernel<<<(NF * 64 + 255) / 256, 256>>>(out);
}

// round 17
// speedup vs baseline: 1.4926x; 1.2147x over previous
#include <cuda_runtime.h>
#include <cuda_bf16.h>
#include <cuda_fp16.h>
#include <math.h>
#include <stdint.h>

#define NF    20000
#define NMB   5000
#define EFFN  100000
#define EMFN  80000
#define DIMV  64
#define KWN   512
#define SLAB  2500
#define NSLAB 8
#define W2N   32768            // KWN * DIMV

#define A_LD  24               // 16 k + 8 pad (ushort)
#define B_LD  136              // 128 n + 8 pad (ushort)

typedef unsigned long long u64t;

// ---------------- device scratch (__device__ globals; no allocations) ----------------
__device__ unsigned short g_h [(size_t)EFFN * KWN];     // 102.4 MB fp16
__device__ unsigned short g_M [(size_t)SLAB * W2N];     // 164 MB fp16
__device__ unsigned short g_W2T_h[(size_t)DIMV * W2N];  // 4 MB  fp16 [d][n=k*64+f]
__device__ unsigned short g_Wk1_h[KWN * KWN];           // 512 KB fp16 [k][n]
__device__ unsigned short g_x_hi[(NF + 512) * DIMV];    // fp16 hi
__device__ unsigned short g_x_lo[(NF + 512) * DIMV];    // fp16 lo
__device__ float    g_q [NF * DIMV];
__device__ float    g_kk[NMB * DIMV];
__device__ float    g_v [NMB * DIMV];
__device__ float    g_c [NF * DIMV];
__device__ float    g_score[EMFN];
__device__ float    g_av[EMFN];
__device__ unsigned g_mkey[NF];
__device__ float    g_z[NF];
__device__ float    g_xc[NF * DIMV];
__device__ float    g_base[NF * DIMV];
__device__ float    g_aggr[NF * DIMV];
__device__ int      g_cnt[NF];
__device__ int      g_off[NF + 1];
__device__ int      g_pos[NF];
__device__ int      g_perm[EFFN];
__device__ float    g_ss[2 * DIMV];

// ---------------- helpers ----------------
__device__ __forceinline__ unsigned kenc(float f) {
    unsigned b = __float_as_uint(f);
    return (b & 0x80000000u) ? ~b : (b | 0x80000000u);
}
__device__ __forceinline__ float kdec(unsigned u) {
    return (u & 0x80000000u) ? __uint_as_float(u ^ 0x80000000u) : __uint_as_float(~u);
}
__device__ __forceinline__ float silu(float y) { return y / (1.f + expf(-y)); }

__device__ __forceinline__ u64t pack_dup(float x) {
    u64t r; asm("mov.b64 %0, {%1, %1};" : "=l"(r) : "r"(__float_as_uint(x))); return r;
}
__device__ __forceinline__ u64t pack2(float lo, float hi) {
    u64t r; asm("mov.b64 %0, {%1, %2};" : "=l"(r) : "r"(__float_as_uint(lo)), "r"(__float_as_uint(hi))); return r;
}
__device__ __forceinline__ void fma2(u64t& d, u64t a, u64t b) {
    asm("fma.rn.f32x2 %0, %1, %2, %0;" : "+l"(d) : "l"(a), "l"(b));
}

__device__ __forceinline__ uint32_t smem_u32(const void* p) {
    uint32_t a;
    asm("{ .reg .u64 t; cvta.to.shared.u64 t, %1; cvt.u32.u64 %0, t; }" : "=r"(a) : "l"(p));
    return a;
}
__device__ __forceinline__ void cpa16(void* dst_smem, const void* src) {
    asm volatile("cp.async.ca.shared.global [%0], [%1], 16;"
                 :: "r"(smem_u32(dst_smem)), "l"(src));
}
#define CPA_COMMIT() asm volatile("cp.async.commit_group;")
#define CPA_WAIT1()  asm volatile("cp.async.wait_group 1;")
#define CPA_WAIT0()  asm volatile("cp.async.wait_group 0;")

__device__ __forceinline__ void ldsm4(uint32_t& r0, uint32_t& r1, uint32_t& r2, uint32_t& r3, uint32_t a) {
    asm volatile("ldmatrix.sync.aligned.m8n8.x4.shared.b16 {%0,%1,%2,%3}, [%4];"
        : "=r"(r0), "=r"(r1), "=r"(r2), "=r"(r3) : "r"(a));
}
__device__ __forceinline__ void ldsm4t(uint32_t& r0, uint32_t& r1, uint32_t& r2, uint32_t& r3, uint32_t a) {
    asm volatile("ldmatrix.sync.aligned.m8n8.x4.trans.shared.b16 {%0,%1,%2,%3}, [%4];"
        : "=r"(r0), "=r"(r1), "=r"(r2), "=r"(r3) : "r"(a));
}
__device__ __forceinline__ void mma_f16(float* c, const uint32_t* a, uint32_t b0, uint32_t b1) {
    asm volatile(
        "mma.sync.aligned.m16n8k16.row.col.f32.f16.f16.f32 "
        "{%0,%1,%2,%3}, {%4,%5,%6,%7}, {%8,%9}, {%0,%1,%2,%3};"
        : "+f"(c[0]), "+f"(c[1]), "+f"(c[2]), "+f"(c[3])
        : "r"(a[0]), "r"(a[1]), "r"(a[2]), "r"(a[3]), "r"(b0), "r"(b1));
}

// fp16 hi/lo split of 8 consecutive floats -> two 16B packets (A side, exact to ~2^-22)
__device__ __forceinline__ void split8h(const float* s, uint4& hi, uint4& lo) {
    unsigned short h[8], l[8];
#pragma unroll
    for (int i = 0; i < 8; i++) {
        float f = s[i];
        __half bh = __float2half_rn(f);
        __half bl = __float2half_rn(f - __half2float(bh));
        h[i] = __half_as_ushort(bh);
        l[i] = __half_as_ushort(bl);
    }
    hi.x = h[0] | ((unsigned)h[1] << 16); hi.y = h[2] | ((unsigned)h[3] << 16);
    hi.z = h[4] | ((unsigned)h[5] << 16); hi.w = h[6] | ((unsigned)h[7] << 16);
    lo.x = l[0] | ((unsigned)l[1] << 16); lo.y = l[2] | ((unsigned)l[3] << 16);
    lo.z = l[4] | ((unsigned)l[5] << 16); lo.w = l[6] | ((unsigned)l[7] << 16);
}

// warp-tile kstep (fp16x2): c[2][8][4] += (Ahi+Alo)[32x16] * B[16x64]
__device__ __forceinline__ void warp_kstep(float c[2][8][4],
        const unsigned short* Ahi, const unsigned short* Alo,
        const unsigned short* Bs,
        int warp_m, int warp_n, int lane) {
    int arow = lane & 15;
    int acol = (lane >> 4) << 3;
    uint32_t ahi[2][4], alo[2][4];
#pragma unroll
    for (int mi = 0; mi < 2; mi++) {
        int r = warp_m * 32 + mi * 16 + arow;
        ldsm4(ahi[mi][0], ahi[mi][1], ahi[mi][2], ahi[mi][3], smem_u32(Ahi + r * A_LD + acol));
        ldsm4(alo[mi][0], alo[mi][1], alo[mi][2], alo[mi][3], smem_u32(Alo + r * A_LD + acol));
    }
#pragma unroll
    for (int nh = 0; nh < 2; nh++) {
        uint32_t b[2][4];
#pragma unroll
        for (int ni = 0; ni < 2; ni++) {
            int ncol = warp_n * 64 + nh * 32 + ni * 16 + acol;
            ldsm4t(b[ni][0], b[ni][1], b[ni][2], b[ni][3], smem_u32(Bs + arow * B_LD + ncol));
        }
#pragma unroll
        for (int mi = 0; mi < 2; mi++)
#pragma unroll
            for (int ni = 0; ni < 2; ni++) {
                int n8 = nh * 4 + ni * 2;
                mma_f16(c[mi][n8],     ahi[mi], b[ni][0], b[ni][1]);
                mma_f16(c[mi][n8 + 1], ahi[mi], b[ni][2], b[ni][3]);
                mma_f16(c[mi][n8],     alo[mi], b[ni][0], b[ni][1]);
                mma_f16(c[mi][n8 + 1], alo[mi], b[ni][2], b[ni][3]);
            }
    }
}

// ---------------- tiny utility kernels ----------------
__global__ void zero_u32(unsigned* p, int n) {
    for (int i = blockIdx.x * blockDim.x + threadIdx.x; i < n; i += gridDim.x * blockDim.x)
        p[i] = 0u;
}

__global__ void conv_wk1(const float* __restrict__ Wk1) {
    int idx = blockIdx.x * blockDim.x + threadIdx.x;
    if (idx >= KWN * KWN) return;
    g_Wk1_h[idx] = __half_as_ushort(__float2half_rn(Wk1[idx]));
}

__global__ void conv_w2t(const float* __restrict__ Wk2) {
    int idx = blockIdx.x * blockDim.x + threadIdx.x;
    if (idx >= DIMV * W2N) return;
    int d = idx >> 15;
    int r = idx & 32767;
    int k = r >> 6;
    int f = r & 63;
    g_W2T_h[idx] = __half_as_ushort(__float2half_rn(Wk2[k * 4096 + d * 64 + f]));
}

__global__ void conv_x(const float* __restrict__ x_flow) {
    int idx = blockIdx.x * blockDim.x + threadIdx.x;
    if (idx >= (NF + 512) * DIMV) return;
    float v = (idx < NF * DIMV) ? x_flow[idx] : 0.f;
    __half bh = __float2half_rn(v);
    __half bl = __float2half_rn(v - __half2float(bh));
    g_x_hi[idx] = __half_as_ushort(bh);
    g_x_lo[idx] = __half_as_ushort(bl);
}

// ---------------- HMMA GEMM 1 (fused h0, pipelined B): h = relu(relu(ea@Wk0+bk0) @ Wk1 + bk1) ----------------
__global__ void __launch_bounds__(256, 2)
gemm_h_mma(const float* __restrict__ ea_ff, const float* __restrict__ Wk0,
           const float* __restrict__ bk0, const float* __restrict__ bk1) {
    __shared__ __align__(16) unsigned short Ahi[2][128 * A_LD], Alo[2][128 * A_LD];
    __shared__ __align__(16) unsigned short Bs[2][16 * B_LD];
    __shared__ float sWk0[6 * KWN];   // 12 KB
    __shared__ float sbk0[KWN];       // 2 KB
    int tid = threadIdx.x, wid = tid >> 5, lane = tid & 31;
    int warp_m = wid & 3, warp_n = wid >> 2;
    int tm = blockIdx.y, tn = blockIdx.x;

    for (int i = tid; i < 6 * KWN; i += 256) sWk0[i] = Wk0[i];
    for (int i = tid; i < KWN; i += 256) sbk0[i] = bk0[i];

    int arow_g = tm * 128 + (tid >> 1);
    float a6[6];
    {
        bool valid = arow_g < EFFN;
        const float* ea = ea_ff + (size_t)(valid ? arow_g : 0) * 6;
#pragma unroll
        for (int j = 0; j < 6; j++) a6[j] = valid ? ea[j] : 0.f;
    }
    __syncthreads();

    int ar = tid >> 1, ac = (tid & 1) * 8;
    int bkr = tid >> 4, bc = (tid & 15) * 8;

    float c[2][8][4];
#pragma unroll
    for (int i = 0; i < 2; i++)
#pragma unroll
        for (int j = 0; j < 8; j++)
#pragma unroll
            for (int q = 0; q < 4; q++) c[i][j][q] = 0.f;

#define HSTAGE_A(s, kc) { \
    float v[8]; \
    _Pragma("unroll") \
    for (int i = 0; i < 8; i++) { \
        int k = (kc) * 16 + ac + i; \
        float sv = sbk0[k]; \
        _Pragma("unroll") \
        for (int j = 0; j < 6; j++) sv = fmaf(a6[j], sWk0[j * KWN + k], sv); \
        v[i] = fmaxf(sv, 0.f); \
    } \
    uint4 hi, lo; split8h(v, hi, lo); \
    *(uint4*)&Ahi[s][ar * A_LD + ac] = hi; \
    *(uint4*)&Alo[s][ar * A_LD + ac] = lo; }

#define HSTAGE_B(s, kc) { \
    size_t src = (size_t)((kc) * 16 + bkr) * KWN + tn * 128 + bc; \
    cpa16(&Bs[s][bkr * B_LD + bc], g_Wk1_h + src); \
    CPA_COMMIT(); }

    HSTAGE_A(0, 0);
    HSTAGE_B(0, 0);
    for (int kc = 0; kc < 32; kc++) {
        int cur = kc & 1, nxt = cur ^ 1;
        if (kc < 31) {
            HSTAGE_A(nxt, kc + 1);
            HSTAGE_B(nxt, kc + 1);
            CPA_WAIT1();
        } else {
            CPA_WAIT0();
        }
        __syncthreads();
        warp_kstep(c, Ahi[cur], Alo[cur], Bs[cur], warp_m, warp_n, lane);
        __syncthreads();
    }
#undef HSTAGE_A
#undef HSTAGE_B

    int rbase = tm * 128 + warp_m * 32 + (lane >> 2);
    int cbase = tn * 128 + warp_n * 64 + (lane & 3) * 2;
#pragma unroll
    for (int mi = 0; mi < 2; mi++) {
#pragma unroll
        for (int n8 = 0; n8 < 8; n8++) {
            int col = cbase + n8 * 8;
            float b0 = bk1[col], b1 = bk1[col + 1];
            int r0 = rbase + mi * 16;
            if (r0 < EFFN) {
                __half2 hv = __floats2half2_rn(fmaxf(c[mi][n8][0] + b0, 0.f),
                                               fmaxf(c[mi][n8][1] + b1, 0.f));
                *(uint32_t*)&g_h[(size_t)r0 * KWN + col] = *(uint32_t*)&hv;
            }
            int r1 = r0 + 8;
            if (r1 < EFFN) {
                __half2 hv = __floats2half2_rn(fmaxf(c[mi][n8][2] + b0, 0.f),
                                               fmaxf(c[mi][n8][3] + b1, 0.f));
                *(uint32_t*)&g_h[(size_t)r1 * KWN + col] = *(uint32_t*)&hv;
            }
        }
    }
}

// ---------------- HMMA GEMM 2 (pipelined): M_slab = x_slab @ W2T, K=64 -> fp16 ----------------
__global__ void __launch_bounds__(256, 2)
gemm_m_mma(int slab) {
    __shared__ __align__(16) unsigned short Ahi[2][128 * A_LD], Alo[2][128 * A_LD];
    __shared__ __align__(16) unsigned short Bs[2][16 * B_LD];
    int tid = threadIdx.x, wid = tid >> 5, lane = tid & 31;
    int warp_m = wid & 3, warp_n = wid >> 2;
    int tm = blockIdx.y, tn = blockIdx.x;

    float c[2][8][4];
#pragma unroll
    for (int i = 0; i < 2; i++)
#pragma unroll
        for (int j = 0; j < 8; j++)
#pragma unroll
            for (int q = 0; q < 4; q++) c[i][j][q] = 0.f;

    int ar = tid >> 1, ac = (tid & 1) * 8;
    int bkr = tid >> 4, bc = (tid & 15) * 8;

#define MSTAGE(s, kc) { \
    size_t asrc = (size_t)(slab * SLAB + tm * 128 + ar) * DIMV + (kc) * 16 + ac; \
    cpa16(&Ahi[s][ar * A_LD + ac], g_x_hi + asrc); \
    cpa16(&Alo[s][ar * A_LD + ac], g_x_lo + asrc); \
    size_t bsrc = (size_t)((kc) * 16 + bkr) * W2N + tn * 128 + bc; \
    cpa16(&Bs[s][bkr * B_LD + bc], g_W2T_h + bsrc); \
    CPA_COMMIT(); }

    MSTAGE(0, 0);
    for (int kc = 0; kc < 4; kc++) {
        int cur = kc & 1;
        if (kc < 3) { MSTAGE(cur ^ 1, kc + 1); CPA_WAIT1(); }
        else        { CPA_WAIT0(); }
        __syncthreads();
        warp_kstep(c, Ahi[cur], Alo[cur], Bs[cur], warp_m, warp_n, lane);
        __syncthreads();
    }
#undef MSTAGE

    int rbase = tm * 128 + warp_m * 32 + (lane >> 2);
    int cbase = tn * 128 + warp_n * 64 + (lane & 3) * 2;
#pragma unroll
    for (int mi = 0; mi < 2; mi++) {
#pragma unroll
        for (int n8 = 0; n8 < 8; n8++) {
            int col = cbase + n8 * 8;
            int r0 = rbase + mi * 16;
            if (r0 < SLAB) {
                __half2 hv = __floats2half2_rn(c[mi][n8][0], c[mi][n8][1]);
                *(uint32_t*)&g_M[(size_t)r0 * W2N + col] = *(uint32_t*)&hv;
            }
            int r1 = r0 + 8;
            if (r1 < SLAB) {
                __half2 hv = __floats2half2_rn(c[mi][n8][2], c[mi][n8][3]);
                *(uint32_t*)&g_M[(size_t)r1 * W2N + col] = *(uint32_t*)&hv;
            }
        }
    }
}

// ---------------- generic tiled SGEMM (FFMA2): small GEMMs ----------------
template <bool RELU>
__global__ void __launch_bounds__(256, 2)
sgemm(const float* __restrict__ A, const float* __restrict__ B,
      const float* __restrict__ bias, float* __restrict__ C,
      int M, int N, int K) {
    __shared__ __align__(16) float As[16][132];
    __shared__ __align__(16) float Bs[16][128];
    int bm = blockIdx.y * 128, bn = blockIdx.x * 128;
    int tid = threadIdx.x;
    int tr = tid >> 4, tc = tid & 15;
    bool k4 = ((K & 3) == 0);

    u64t acc2[8][4];
#pragma unroll
    for (int i = 0; i < 8; i++)
#pragma unroll
        for (int j = 0; j < 4; j++) acc2[i][j] = 0ull;

    for (int kt = 0; kt < K; kt += 16) {
#pragma unroll
        for (int l = 0; l < 2; l++) {
            int lin = tid + l * 256;
            int row = lin >> 2;
            int kq  = (lin & 3) * 4;
            float4 v = make_float4(0.f, 0.f, 0.f, 0.f);
            int gr = bm + row;
            if (gr < M) {
                int k0 = kt + kq;
                if (k4 && k0 + 3 < K) {
                    v = *(const float4*)&A[(size_t)gr * K + k0];
                } else {
                    float t0[4] = {0.f, 0.f, 0.f, 0.f};
#pragma unroll
                    for (int i = 0; i < 4; i++)
                        if (k0 + i < K) t0[i] = A[(size_t)gr * K + k0 + i];
                    v = make_float4(t0[0], t0[1], t0[2], t0[3]);
                }
            }
            As[kq + 0][row] = v.x; As[kq + 1][row] = v.y;
            As[kq + 2][row] = v.z; As[kq + 3][row] = v.w;
        }
#pragma unroll
        for (int l = 0; l < 2; l++) {
            int lin = tid + l * 256;
            int kr = lin >> 5;
            int nq = (lin & 31) * 4;
            float4 v = make_float4(0.f, 0.f, 0.f, 0.f);
            int gk = kt + kr, gn = bn + nq;
            if (gk < K && gn + 3 < N)
                v = *(const float4*)&B[(size_t)gk * N + gn];
            *(float4*)&Bs[kr][nq] = v;
        }
        __syncthreads();
#pragma unroll
        for (int k = 0; k < 16; k++) {
            float a[8];
            *(float4*)&a[0] = *(const float4*)&As[k][tr * 8];
            *(float4*)&a[4] = *(const float4*)&As[k][tr * 8 + 4];
            u64t b2[4];
            const u64t* bp = (const u64t*)&Bs[k][tc * 8];
            b2[0] = bp[0]; b2[1] = bp[1]; b2[2] = bp[2]; b2[3] = bp[3];
#pragma unroll
            for (int i = 0; i < 8; i++) {
                u64t ad = pack_dup(a[i]);
#pragma unroll
                for (int j = 0; j < 4; j++) fma2(acc2[i][j], ad, b2[j]);
            }
        }
        __syncthreads();
    }
#pragma unroll
    for (int i = 0; i < 8; i++) {
        int gr = bm + tr * 8 + i;
        if (gr >= M) continue;
#pragma unroll
        for (int j = 0; j < 4; j++) {
            float2 p = *(float2*)&acc2[i][j];
            int gn0 = bn + tc * 8 + 2 * j;
#pragma unroll
            for (int s = 0; s < 2; s++) {
                int gn = gn0 + s;
                if (gn >= N) continue;
                float v = (s == 0) ? p.x : p.y;
                if (bias) v += bias[gn];
                if (RELU) v = fmaxf(v, 0.f);
                C[(size_t)gr * N + gn] = v;
            }
        }
    }
}

// ---------------- attention path ----------------
__global__ void score_kernel(const int* __restrict__ ei_mf, const float* __restrict__ ea_mf,
                             const float* __restrict__ We) {
    __shared__ float sWe[6 * 64];
    int tid = threadIdx.x;
    for (int i = tid; i < 6 * 64; i += blockDim.x) sWe[i] = We[i];
    __syncthreads();
    int e = blockIdx.x * 8 + (tid >> 5);
    if (e >= EMFN) return;
    int l = tid & 31;
    int src = ei_mf[e];
    int dst = ei_mf[EMFN + e];
    float ke0 = g_kk[src * 64 + l];
    float ke1 = g_kk[src * 64 + 32 + l];
#pragma unroll
    for (int j = 0; j < 6; j++) {
        float ea = ea_mf[e * 6 + j];
        ke0 = fmaf(ea, sWe[j * 64 + l], ke0);
        ke1 = fmaf(ea, sWe[j * 64 + 32 + l], ke1);
    }
    float s = g_q[dst * 64 + l] * ke0 + g_q[dst * 64 + 32 + l] * ke1;
#pragma unroll
    for (int off = 16; off; off >>= 1) s += __shfl_down_sync(0xffffffffu, s, off);
    if (l == 0) {
        s *= 0.125f;
        g_score[e] = s;
        atomicMax(&g_mkey[dst], kenc(s));
    }
}

__global__ void exp_kernel(const int* __restrict__ ei_mf) {
    int e = blockIdx.x * blockDim.x + threadIdx.x;
    if (e >= EMFN) return;
    int dst = ei_mf[EMFN + e];
    float a = expf(g_score[e] - kdec(g_mkey[dst]));
    g_av[e] = a;
    atomicAdd(&g_z[dst], a);
}

__global__ void xcacc_kernel(const int* __restrict__ ei_mf) {
    int e = blockIdx.x * 8 + (threadIdx.x >> 5);
    if (e >= EMFN) return;
    int l = threadIdx.x & 31;
    int src = ei_mf[e];
    int dst = ei_mf[EMFN + e];
    float alpha = g_av[e] / (g_z[dst] + 1e-9f);
    atomicAdd(&g_xc[dst * 64 + l],      alpha * g_v[src * 64 + l]);
    atomicAdd(&g_xc[dst * 64 + 32 + l], alpha * g_v[src * 64 + 32 + l]);
}

__global__ void dual64_kernel(const float* __restrict__ x, const float* __restrict__ Wroot,
                              const float* __restrict__ broot, const float* __restrict__ Wo,
                              const float* __restrict__ bo) {
    __shared__ float sWr[64 * 64], sWo[64 * 64], sx[4][64], sxc[4][64];
    int tid = threadIdx.x;
    for (int i = tid; i < 4096; i += 256) { sWr[i] = Wroot[i]; sWo[i] = Wo[i]; }
    int r0 = blockIdx.x * 4;
    {
        int rr = tid >> 6, cc = tid & 63;
        int gr = r0 + rr;
        sx[rr][cc]  = (gr < NF) ? x[gr * 64 + cc]    : 0.f;
        sxc[rr][cc] = (gr < NF) ? g_xc[gr * 64 + cc] : 0.f;
    }
    __syncthreads();
    int rr = tid >> 6, cc = tid & 63;
    int gr = r0 + rr;
    if (gr < NF) {
        float s = broot[cc] + bo[cc];
#pragma unroll 8
        for (int d = 0; d < 64; d++)
            s += sx[rr][d] * sWr[d * 64 + cc] + sxc[rr][d] * sWo[d * 64 + cc];
        g_base[gr * 64 + cc] = s;
    }
}

// ---------------- CSR by src over ff-edges ----------------
__global__ void cnt_kernel(const int* __restrict__ ei_ff) {
    int e = blockIdx.x * blockDim.x + threadIdx.x;
    if (e < EFFN) atomicAdd(&g_cnt[ei_ff[e]], 1);
}

__global__ void scan_kernel() {
    __shared__ int s[1024];
    __shared__ int carry;
    int tid = threadIdx.x;
    if (tid == 0) carry = 0;
    __syncthreads();
    for (int base = 0; base < NF; base += 1024) {
        int i = base + tid;
        int v = (i < NF) ? g_cnt[i] : 0;
        s[tid] = v;
        __syncthreads();
        for (int off = 1; off < 1024; off <<= 1) {
            int t = (tid >= off) ? s[tid - off] : 0;
            __syncthreads();
            s[tid] += t;
            __syncthreads();
        }
        if (i < NF) { int ex = carry + s[tid] - v; g_off[i] = ex; g_pos[i] = ex; }
        __syncthreads();
        if (tid == 0) carry += s[1023];
        __syncthreads();
    }
    if (tid == 0) g_off[NF] = carry;
}

__global__ void fill_kernel(const int* __restrict__ ei_ff) {
    int e = blockIdx.x * blockDim.x + threadIdx.x;
    if (e < EFFN) {
        int p = atomicAdd(&g_pos[ei_ff[e]], 1);
        g_perm[p] = e;
    }
}

// ---------------- phase B: per-node msg = h[e] @ M[node] -> atomic aggr[dst] ----------------
__global__ void __launch_bounds__(256)
msg_kernel(const int* __restrict__ ei_ff, int slab) {
    __shared__ __align__(16) float Ms[128][64];
    __shared__ __align__(16) float hs[8][128];
    __shared__ float red[8][4][64];
    int tid = threadIdx.x;
    int nl = blockIdx.x;
    int n  = slab * SLAB + nl;
    int begin = g_off[n], end = g_off[n + 1];
    if (begin == end) return;
    int f = tid & 63, slice = tid >> 6;
    const unsigned short* Mrow = g_M + (size_t)nl * W2N;
    float cbias = g_c[n * 64 + f];

    for (int e0 = begin; e0 < end; e0 += 8) {
        int ec = min(8, end - e0);
        u64t acc2[8];
#pragma unroll
        for (int j = 0; j < 8; j++) acc2[j] = 0ull;

        for (int kt = 0; kt < 4; kt++) {
#pragma unroll
            for (int l = 0; l < 4; l++) {
                int lin = tid + l * 256;
                int k  = lin >> 3;
                int fq = (lin & 7) * 8;
                uint4 pk = *(const uint4*)&Mrow[(size_t)(kt * 128 + k) * 64 + fq];
                const __half2* hp = (const __half2*)&pk;
                float2 f0 = __half22float2(hp[0]);
                float2 f1 = __half22float2(hp[1]);
                float2 f2 = __half22float2(hp[2]);
                float2 f3 = __half22float2(hp[3]);
                *(float4*)&Ms[k][fq]     = make_float4(f0.x, f0.y, f1.x, f1.y);
                *(float4*)&Ms[k][fq + 4] = make_float4(f2.x, f2.y, f3.x, f3.y);
            }
            if (tid < 128) {
                int j  = tid >> 4;
                int kq = (tid & 15) * 8;
                uint4 pk = make_uint4(0, 0, 0, 0);
                if (j < ec) {
                    int e = g_perm[e0 + j];
                    pk = *(const uint4*)&g_h[(size_t)e * KWN + kt * 128 + kq];
                }
                const __half2* hp = (const __half2*)&pk;
                float2 f0 = __half22float2(hp[0]);
                float2 f1 = __half22float2(hp[1]);
                float2 f2 = __half22float2(hp[2]);
                float2 f3 = __half22float2(hp[3]);
                *(float4*)&hs[j][kq]     = make_float4(f0.x, f0.y, f1.x, f1.y);
                *(float4*)&hs[j][kq + 4] = make_float4(f2.x, f2.y, f3.x, f3.y);
            }
            __syncthreads();
#pragma unroll
            for (int kk2 = 0; kk2 < 16; kk2++) {
                int k = slice * 32 + kk2 * 2;
                u64t m2 = pack2(Ms[k][f], Ms[k + 1][f]);
#pragma unroll
                for (int j = 0; j < 8; j++) {
                    u64t h2 = *(const u64t*)&hs[j][k];
                    fma2(acc2[j], h2, m2);
                }
            }
            __syncthreads();
        }
        for (int j = 0; j < ec; j++) {
            float2 p = *(float2*)&acc2[j];
            red[j][slice][f] = p.x + p.y;
        }
        __syncthreads();
        for (int jb = 0; jb < ec; jb += 4) {
            int j = jb + (tid >> 6);
            if (j < ec) {
                float s = red[j][0][f] + red[j][1][f] + red[j][2][f] + red[j][3][f] + cbias;
                int e = g_perm[e0 + j];
                int dst = ei_ff[EFFN + e];
                atomicAdd(&g_aggr[dst * 64 + f], s);
            }
        }
        __syncthreads();
    }
}

// ---------------- FiLM epilogue ----------------
__global__ void ss_kernel(const float* __restrict__ tau, const float* __restrict__ Wt1,
                          const float* __restrict__ bt1, const float* __restrict__ Wt2,
                          const float* __restrict__ bt2) {
    __shared__ float temb[64];
    int tid = threadIdx.x;
    if (tid < 64) temb[tid] = silu(tau[0] * Wt1[tid] + bt1[tid]);
    __syncthreads();
    if (tid < 128) {
        float s = bt2[tid];
        for (int d = 0; d < 64; d++) s += temb[d] * Wt2[d * 128 + tid];
        g_ss[tid] = s;
    }
}

__global__ void final_kernel(float* __restrict__ out) {
    int idx = blockIdx.x * blockDim.x + threadIdx.x;
    if (idx >= NF * 64) return;
    int fcol = idx & 63;
    float g = g_base[idx] + g_aggr[idx];
    g = fmaxf(g, 0.f);
    float y = g * (1.f + g_ss[fcol]) + g_ss[64 + fcol];
    out[idx] = silu(y);
}

// ---------------- host ----------------
extern "C" void kernel_launch(void* const* d_in, const int* in_sizes, int n_in,
                              void* d_out, int out_size) {
    const float* x_flow = (const float*)d_in[0];
    const float* x_memb = (const float*)d_in[1];
    const int *ei_ff, *ei_mf;
    const float *ea_ff, *ea_mf, *tau;
    if (in_sizes[2] == 2 * EFFN) {
        ei_ff = (const int*)d_in[2];  ea_ff = (const float*)d_in[3];
        ei_mf = (const int*)d_in[4];  ea_mf = (const float*)d_in[5];
        tau   = (const float*)d_in[6];
    } else {
        ea_ff = (const float*)d_in[2]; ea_mf = (const float*)d_in[3];
        tau   = (const float*)d_in[4];
        ei_ff = (const int*)d_in[5];   ei_mf = (const int*)d_in[6];
    }
    const float* Wk0   = (const float*)d_in[7];
    const float* bk0   = (const float*)d_in[8];
    const float* Wk1   = (const float*)d_in[9];
    const float* bk1   = (const float*)d_in[10];
    const float* Wk2   = (const float*)d_in[11];
    const float* bk2   = (const float*)d_in[12];
    const float* Wroot = (const float*)d_in[13];
    const float* broot = (const float*)d_in[14];
    const float* Wq    = (const float*)d_in[15];
    const float* Wkk   = (const float*)d_in[16];
    const float* Wv    = (const float*)d_in[17];
    const float* We    = (const float*)d_in[18];
    const float* Wo    = (const float*)d_in[19];
    const float* bo    = (const float*)d_in[20];
    const float* Wt1   = (const float*)d_in[21];
    const float* bt1   = (const float*)d_in[22];
    const float* Wt2   = (const float*)d_in[23];
    const float* bt2   = (const float*)d_in[24];
    float* out = (float*)d_out;

    unsigned *p_mkey; float *p_z, *p_xc, *p_aggr; int* p_cnt;
    cudaGetSymbolAddress((void**)&p_mkey, g_mkey);
    cudaGetSymbolAddress((void**)&p_z,    g_z);
    cudaGetSymbolAddress((void**)&p_xc,   g_xc);
    cudaGetSymbolAddress((void**)&p_aggr, g_aggr);
    cudaGetSymbolAddress((void**)&p_cnt,  g_cnt);
    float *p_q, *p_kk, *p_v, *p_c;
    cudaGetSymbolAddress((void**)&p_q,   g_q);
    cudaGetSymbolAddress((void**)&p_kk,  g_kk);
    cudaGetSymbolAddress((void**)&p_v,   g_v);
    cudaGetSymbolAddress((void**)&p_c,   g_c);

    // -- weight conversion first; gemm_h early so profiler window lands on it --
    conv_w2t<<<(DIMV * W2N + 255) / 256, 256>>>(Wk2);                 // 0
    conv_wk1<<<(KWN * KWN + 255) / 256, 256>>>(Wk1);                  // 1
    conv_x<<<((NF + 512) * DIMV + 255) / 256, 256>>>(x_flow);         // 2
    gemm_h_mma<<<dim3(4, (EFFN + 127) / 128), 256>>>(ea_ff, Wk0, bk0, bk1); // 3
    gemm_m_mma<<<dim3(W2N / 128, (SLAB + 127) / 128), 256>>>(0);      // 4

    // init zeros
    zero_u32<<<640, 256>>>((unsigned*)p_aggr, NF * 64);
    zero_u32<<<160, 256>>>(p_mkey, NF);
    zero_u32<<<160, 256>>>((unsigned*)p_z, NF);
    zero_u32<<<640, 256>>>((unsigned*)p_xc, NF * 64);
    zero_u32<<<160, 256>>>((unsigned*)p_cnt, NF);

    // small GEMMs: q, k, v, c
    {
        dim3 g1(1, (NF + 127) / 128);
        sgemm<false><<<g1, 256>>>(x_flow, Wq, nullptr, p_q, NF, 64, 64);
        dim3 g2(1, (NMB + 127) / 128);
        sgemm<false><<<g2, 256>>>(x_memb, Wkk, nullptr, p_kk, NMB, 64, 64);
        sgemm<false><<<g2, 256>>>(x_memb, Wv, nullptr, p_v, NMB, 64, 64);
        sgemm<false><<<g1, 256>>>(x_flow, bk2, nullptr, p_c, NF, 64, 64);
    }

    // attention path
    score_kernel<<<(EMFN + 7) / 8, 256>>>(ei_mf, ea_mf, We);
    exp_kernel<<<(EMFN + 255) / 256, 256>>>(ei_mf);
    xcacc_kernel<<<(EMFN + 7) / 8, 256>>>(ei_mf);
    dual64_kernel<<<(NF + 3) / 4, 256>>>(x_flow, Wroot, broot, Wo, bo);

    // CSR by src
    cnt_kernel<<<(EFFN + 255) / 256, 256>>>(ei_ff);
    scan_kernel<<<1, 1024>>>();
    fill_kernel<<<(EFFN + 255) / 256, 256>>>(ei_ff);

    // slab 0 msg (gemm_m slab0 already launched above), then remaining slabs
    msg_kernel<<<SLAB, 256>>>(ei_ff, 0);
    for (int s = 1; s < NSLAB; s++) {
        gemm_m_mma<<<dim3(W2N / 128, (SLAB + 127) / 128), 256>>>(s);
        msg_kernel<<<SLAB, 256>>>(ei_ff, s);
    }

    // FiLM epilogue
    ss_kernel<<<1, 128>>>(tau, Wt1, bt1, Wt2, bt2);
    final_kernel<<<(NF * 64 + 255) / 256, 256>>>(out);
}